// round 7
// baseline (speedup 1.0000x reference)
#include <cuda_runtime.h>

#define BATCH 1024
#define NIN   1152
#define DIN   8
#define NOUT  10
#define DOUT  16
#define QTOT  (NIN * DIN)        // 9216
#define NCHUNK 36
#define CI     (NIN / NCHUNK)    // 32 input capsules per block
#define TB     32                // batches per CTA (4 per thread: 8 bl x 4 dq)
#define BTILES (BATCH / TB)      // 32
#define SI     4                 // i's per W sub-tile
#define NSUB   (CI / SI)         // 8
#define XROW   12                // padded floats per (i,b) x-row in smem (48B: bank-clean)

#define WS_FLOATS (SI * NOUT * 128)          // 5120 floats per W buffer (20KB)
#define XS_FLOATS (CI * TB * XROW)           // 12288 floats (48KB)
#define SMEM_BYTES ((2 * WS_FLOATS + XS_FLOATS) * 4)   // 88KB

typedef unsigned long long u64;

// Static device scratch (no allocations allowed)
__device__ float g_x2[NIN * BATCH * DIN];               // x regrouped: [i][b][e] (36MB)
__device__ float g_Wt[NIN * NOUT * DIN * DOUT];         // W^T: [i][n][e][d]
__device__ float g_partial[NCHUNK][BATCH][NOUT][DOUT];
__device__ float g_pden[NCHUNK][BATCH][NOUT];
__device__ float g_vsum[BATCH][NOUT][DOUT];

// ---- packed f32x2 helpers ----
__device__ __forceinline__ u64 fma2(u64 a, u64 b, u64 c) {
    u64 d; asm("fma.rn.f32x2 %0,%1,%2,%3;" : "=l"(d) : "l"(a), "l"(b), "l"(c)); return d;
}
__device__ __forceinline__ u64 mul2(u64 a, u64 b) {
    u64 d; asm("mul.rn.f32x2 %0,%1,%2;" : "=l"(d) : "l"(a), "l"(b)); return d;
}
__device__ __forceinline__ u64 dup2(float x) {
    u64 d; asm("mov.b64 %0,{%1,%1};" : "=l"(d) : "f"(x)); return d;
}
__device__ __forceinline__ float hadd2(u64 a) {
    float lo, hi; asm("mov.b64 {%0,%1},%2;" : "=f"(lo), "=f"(hi) : "l"(a)); return lo + hi;
}

// ---- cp.async helpers ----
__device__ __forceinline__ void cpa16(void* smem_dst, const void* gmem_src) {
    unsigned s = (unsigned)__cvta_generic_to_shared(smem_dst);
    asm volatile("cp.async.cg.shared.global [%0], [%1], 16;" :: "r"(s), "l"(gmem_src));
}
__device__ __forceinline__ void cpa_commit() { asm volatile("cp.async.commit_group;"); }
template <int N> __device__ __forceinline__ void cpa_wait() {
    asm volatile("cp.async.wait_group %0;" :: "n"(N));
}

// ---- prep: x[b][i*8+e] -> g_x2[i][b][e]  AND  W[in][d][e] -> g_Wt[in][e][d] ----
#define XT_BLOCKS ((QTOT / 64) * (BATCH / 32))   // 144*32 = 4608
#define WT_BLOCKS 720
__global__ void prep(const float* __restrict__ x, const float* __restrict__ W)
{
    if (blockIdx.x < XT_BLOCKS) {
        __shared__ float t[32 * 64];
        const int tile = blockIdx.x;
        const int q0 = (tile % (QTOT / 64)) * 64;    // 8 i's
        const int b0 = (tile / (QTOT / 64)) * 32;
        const int i0 = q0 / 8;
#pragma unroll
        for (int k = 0; k < 8; k++) {
            const int idx = threadIdx.x + k * 256;   // 2048 elems
            const int r = idx >> 6, c = idx & 63;
            t[r * 64 + c] = x[(size_t)(b0 + r) * QTOT + q0 + c];
        }
        __syncthreads();
#pragma unroll
        for (int k = 0; k < 8; k++) {
            const int idx = threadIdx.x + k * 256;
            const int e = idx & 7, bb = (idx >> 3) & 31, il = idx >> 8;
            g_x2[(size_t)(i0 + il) * BATCH * 8 + (size_t)(b0 + bb) * 8 + e] =
                t[bb * 64 + il * 8 + e];
        }
    } else {
        const int wb = blockIdx.x - XT_BLOCKS;
#pragma unroll
        for (int k = 0; k < 8; k++) {
            const int g = wb * 2048 + k * 256 + threadIdx.x;
            const int d = g & 15;
            const int e = (g >> 4) & 7;
            const int in = g >> 7;
            g_Wt[g] = W[(size_t)in * 128 + d * 8 + e];
        }
    }
}

// ---- One routing pass ----
// warp = n. lane = dq*8 + bl. Thread: batches {bl+8k, k<4}, d in [dq*4, dq*4+4).
// W per e: one LDS.128 (4 distinct 16B chunks across dq, broadcast across bl).
// x per (k, e-half): one LDS.128 (8 distinct batches at 48B stride: conflict-free).
template <bool FIRST>
__global__ void __launch_bounds__(320, 2)
route_pass()
{
    extern __shared__ float sm[];
    float* ws0 = sm;                       // W buffers [2][SI*NOUT*128]
    float* xs  = sm + 2 * WS_FLOATS;       // x tile [CI][TB][XROW]

    const int tid  = threadIdx.x;
    const int n    = tid >> 5;
    const int lane = tid & 31;
    const int dq   = lane >> 3;            // d-quarter 0..3
    const int bl   = lane & 7;             // batch-lane 0..7
    const int i0   = blockIdx.x * CI;
    const int b0   = blockIdx.y * TB;

    // ---- stage x tile: CI*TB rows of 32B (2 chunks) into padded 48B rows ----
    {
        const float* src = g_x2 + (size_t)i0 * BATCH * 8 + (size_t)b0 * 8;
#pragma unroll
        for (int k = 0; k < 7; k++) {
            const int idx = tid + k * 320;         // 2048 chunks
            if (idx < CI * TB * 2) {
                const int row = idx >> 1, c = idx & 1;
                // src rows for this CTA: i-local * (BATCH*8) + b-local * 8
                const int il = row >> 5, lb = row & 31;
                cpa16(xs + (row * XROW + c * 4),
                      src + (size_t)il * BATCH * 8 + lb * 8 + c * 4);
            }
        }
    }
    // ---- prefetch W sub-tile 0 ----
    const float* __restrict__ wbase = g_Wt + (size_t)i0 * NOUT * 128;
#pragma unroll
    for (int k = 0; k < 4; k++)
        cpa16(ws0 + (tid + k * 320) * 4, wbase + (size_t)(tid + k * 320) * 4);
    cpa_commit();

    u64 vs[4][2];
    if (!FIRST) {
#pragma unroll
        for (int k = 0; k < 4; k++) {
            ulonglong2 t = *reinterpret_cast<const ulonglong2*>(&g_vsum[b0 + bl + 8 * k][n][dq * 4]);
            vs[k][0] = t.x; vs[k][1] = t.y;
        }
    }

    u64 acc[4][2];
#pragma unroll
    for (int k = 0; k < 4; k++) { acc[k][0] = 0ull; acc[k][1] = 0ull; }
    float accd[4] = {0.f, 0.f, 0.f, 0.f};

    for (int s = 0; s < NSUB; s++) {
        if (s + 1 < NSUB) {
            float* dst = ws0 + ((s + 1) & 1) * WS_FLOATS;
            const float* src = wbase + (size_t)(s + 1) * WS_FLOATS;
#pragma unroll
            for (int k = 0; k < 4; k++)
                cpa16(dst + (tid + k * 320) * 4, src + (size_t)(tid + k * 320) * 4);
            cpa_commit();
            cpa_wait<1>();
        } else {
            cpa_wait<0>();
        }
        __syncthreads();

        const float* __restrict__ wsb = ws0 + (s & 1) * WS_FLOATS;
        const float* __restrict__ xsb = xs + s * SI * TB * XROW;

        for (int ii = 0; ii < SI; ii++) {
            const float* __restrict__ wp = wsb + (ii * NOUT + n) * 128 + dq * 4;
            const float* __restrict__ xp = xsb + ii * TB * XROW;

            if (FIRST) {
                // accumulate x*W straight into acc (uniform weights)
#pragma unroll
                for (int h = 0; h < 2; h++) {
                    const ulonglong2 w0 = *reinterpret_cast<const ulonglong2*>(wp + (h * 4 + 0) * 16);
                    const ulonglong2 w1 = *reinterpret_cast<const ulonglong2*>(wp + (h * 4 + 1) * 16);
                    const ulonglong2 w2 = *reinterpret_cast<const ulonglong2*>(wp + (h * 4 + 2) * 16);
                    const ulonglong2 w3 = *reinterpret_cast<const ulonglong2*>(wp + (h * 4 + 3) * 16);
#pragma unroll
                    for (int k = 0; k < 4; k++) {
                        const float4 xa = *reinterpret_cast<const float4*>(xp + (bl + 8 * k) * XROW + h * 4);
                        acc[k][0] = fma2(dup2(xa.x), w0.x, acc[k][0]);
                        acc[k][1] = fma2(dup2(xa.x), w0.y, acc[k][1]);
                        acc[k][0] = fma2(dup2(xa.y), w1.x, acc[k][0]);
                        acc[k][1] = fma2(dup2(xa.y), w1.y, acc[k][1]);
                        acc[k][0] = fma2(dup2(xa.z), w2.x, acc[k][0]);
                        acc[k][1] = fma2(dup2(xa.z), w2.y, acc[k][1]);
                        acc[k][0] = fma2(dup2(xa.w), w3.x, acc[k][0]);
                        acc[k][1] = fma2(dup2(xa.w), w3.y, acc[k][1]);
                    }
                }
            } else {
                u64 u[4][2];
#pragma unroll
                for (int h = 0; h < 2; h++) {
                    const ulonglong2 w0 = *reinterpret_cast<const ulonglong2*>(wp + (h * 4 + 0) * 16);
                    const ulonglong2 w1 = *reinterpret_cast<const ulonglong2*>(wp + (h * 4 + 1) * 16);
                    const ulonglong2 w2 = *reinterpret_cast<const ulonglong2*>(wp + (h * 4 + 2) * 16);
                    const ulonglong2 w3 = *reinterpret_cast<const ulonglong2*>(wp + (h * 4 + 3) * 16);
#pragma unroll
                    for (int k = 0; k < 4; k++) {
                        const float4 xa = *reinterpret_cast<const float4*>(xp + (bl + 8 * k) * XROW + h * 4);
                        if (h == 0) {
                            u[k][0] = mul2(dup2(xa.x), w0.x);
                            u[k][1] = mul2(dup2(xa.x), w0.y);
                        } else {
                            u[k][0] = fma2(dup2(xa.x), w0.x, u[k][0]);
                            u[k][1] = fma2(dup2(xa.x), w0.y, u[k][1]);
                        }
                        u[k][0] = fma2(dup2(xa.y), w1.x, u[k][0]);
                        u[k][1] = fma2(dup2(xa.y), w1.y, u[k][1]);
                        u[k][0] = fma2(dup2(xa.z), w2.x, u[k][0]);
                        u[k][1] = fma2(dup2(xa.z), w2.y, u[k][1]);
                        u[k][0] = fma2(dup2(xa.w), w3.x, u[k][0]);
                        u[k][1] = fma2(dup2(xa.w), w3.y, u[k][1]);
                    }
                }
#pragma unroll
                for (int k = 0; k < 4; k++) {
                    u64 l2 = mul2(u[k][0], vs[k][0]);
                    l2 = fma2(u[k][1], vs[k][1], l2);
                    float lq = hadd2(l2);               // quarter-logit
                    lq += __shfl_xor_sync(0xffffffffu, lq, 8);
                    lq += __shfl_xor_sync(0xffffffffu, lq, 16);
                    const float wgt = __expf(lq);        // logits O(10): no shift needed
                    const u64 wd = dup2(wgt);
                    acc[k][0] = fma2(wd, u[k][0], acc[k][0]);
                    acc[k][1] = fma2(wd, u[k][1], acc[k][1]);
                    accd[k] += wgt;
                }
            }
        }
        __syncthreads();   // all warps done with buf[s&1] before refill at s+1
    }

#pragma unroll
    for (int k = 0; k < 4; k++) {
        *reinterpret_cast<ulonglong2*>(&g_partial[blockIdx.x][b0 + bl + 8 * k][n][dq * 4]) =
            make_ulonglong2(acc[k][0], acc[k][1]);
    }
    if (!FIRST && dq == 0) {
#pragma unroll
        for (int k = 0; k < 4; k++)
            g_pden[blockIdx.x][b0 + bl + 8 * k][n] = accd[k];
    }
}

// ---- Reduce partials, squash, update Vsum / write output ----
template <bool FIRST, bool LAST>
__global__ void __launch_bounds__(NOUT * DOUT)
squash_update(float* __restrict__ out)
{
    const int b = blockIdx.x;
    const int tid = threadIdx.x;
    const int n = tid >> 4;
    const int d = tid & 15;

    float num = 0.0f;
#pragma unroll
    for (int c = 0; c < NCHUNK; c++) num += g_partial[c][b][n][d];

    float den;
    if (FIRST) {
        den = (float)NIN;          // uniform weights on pass 0
    } else {
        den = 0.0f;
#pragma unroll
        for (int c = 0; c < NCHUNK; c++) den += g_pden[c][b][n];
    }

    const float s = num / den;

    float s2 = s * s;
#pragma unroll
    for (int off = 8; off; off >>= 1) s2 += __shfl_xor_sync(0xffffffffu, s2, off);

    const float scale = s2 / (1.0f + s2) * rsqrtf(s2 + 1e-7f);
    const float v = scale * s;

    if (LAST)       out[((size_t)b * NOUT + n) * DOUT + d] = v;
    else if (FIRST) g_vsum[b][n][d] = v;
    else            g_vsum[b][n][d] += v;
}

extern "C" void kernel_launch(void* const* d_in, const int* in_sizes, int n_in,
                              void* d_out, int out_size)
{
    const float* x;
    const float* W;
    if (in_sizes[0] == BATCH * NIN * DIN) { x = (const float*)d_in[0]; W = (const float*)d_in[1]; }
    else                                  { x = (const float*)d_in[1]; W = (const float*)d_in[0]; }
    float* out = (float*)d_out;

    static bool attr_done = false;
    if (!attr_done) {
        cudaFuncSetAttribute(route_pass<true >, cudaFuncAttributeMaxDynamicSharedMemorySize, SMEM_BYTES);
        cudaFuncSetAttribute(route_pass<false>, cudaFuncAttributeMaxDynamicSharedMemorySize, SMEM_BYTES);
        attr_done = true;
    }

    prep<<<XT_BLOCKS + WT_BLOCKS, 256>>>(x, W);

    dim3 grid(NCHUNK, BTILES);
    const int threads = 320;

    route_pass<true ><<<grid, threads, SMEM_BYTES>>>();
    squash_update<true , false><<<BATCH, NOUT * DOUT>>>(out);

    route_pass<false><<<grid, threads, SMEM_BYTES>>>();
    squash_update<false, false><<<BATCH, NOUT * DOUT>>>(out);

    route_pass<false><<<grid, threads, SMEM_BYTES>>>();   // <- ncu capture slot (launch #5)
    squash_update<false, true ><<<BATCH, NOUT * DOUT>>>(out);
}

// round 9
// speedup vs baseline: 1.2830x; 1.2830x over previous
#include <cuda_runtime.h>
#include <cuda_bf16.h>
#include <cstdint>

#define BATCH 1024
#define NIN   1152
#define DIN   8
#define NOUT  10
#define DOUT  16
#define QTOT  (NIN * DIN)        // 9216
#define NCHUNK 36
#define CI     (NIN / NCHUNK)    // 32 input capsules per chunk
#define TB     32
#define BTILES (BATCH / TB)      // 32
#define SI     4
#define NSUB   (CI / SI)         // 8

#define WS_FLOATS (SI * NOUT * 128)      // 20KB per W buffer
#define XS_FLOATS (CI * DIN * TB)        // 32KB
#define SMEM_BYTES ((2 * WS_FLOATS + XS_FLOATS) * 4)   // 72KB

typedef unsigned long long u64;

// ---------------- static device scratch ----------------
__device__ float g_xt[QTOT][BATCH];                      // x^T (passes 1-2)
__device__ float g_Wt[NIN * NOUT * DIN * DOUT];          // W^T [i][n][e][d]
__device__ float g_partial[NCHUNK][BATCH][NOUT][DOUT];
__device__ float g_pden[NCHUNK][BATCH][NOUT];
__device__ float g_vsum[BATCH][NOUT][DOUT];
// bf16 operands for pass-0 mma.sync GEMM. slab = 2 i's = one K=16 step.
// q index (0..7): i = slab*2 + (q&1), e = (q>>1)*2; value = bf16 pair (e, e+1).
// This makes fragment pairs (k, k+8-group) adjacent -> LDG.64 per fragment half.
#define GSLABS_TOT (NIN / 2)                             // 576
__device__ uint32_t g_xpair[GSLABS_TOT * BATCH * 8];     // A: [slab][b][q]
__device__ uint32_t g_Wbf[GSLABS_TOT * 160 * 8];         // B: [slab][nd][q]

// ---------------- f32x2 helpers ----------------
__device__ __forceinline__ u64 fma2(u64 a, u64 b, u64 c) {
    u64 d; asm("fma.rn.f32x2 %0,%1,%2,%3;" : "=l"(d) : "l"(a), "l"(b), "l"(c)); return d;
}
__device__ __forceinline__ u64 mul2(u64 a, u64 b) {
    u64 d; asm("mul.rn.f32x2 %0,%1,%2;" : "=l"(d) : "l"(a), "l"(b)); return d;
}
__device__ __forceinline__ u64 dup2(float x) {
    u64 d; asm("mov.b64 %0,{%1,%1};" : "=l"(d) : "f"(x)); return d;
}
__device__ __forceinline__ float hadd2(u64 a) {
    float lo, hi; asm("mov.b64 {%0,%1},%2;" : "=f"(lo), "=f"(hi) : "l"(a)); return lo + hi;
}

// ---------------- cp.async ----------------
__device__ __forceinline__ void cpa16(void* smem_dst, const void* gmem_src) {
    unsigned s = (unsigned)__cvta_generic_to_shared(smem_dst);
    asm volatile("cp.async.cg.shared.global [%0], [%1], 16;" :: "r"(s), "l"(gmem_src));
}
__device__ __forceinline__ void cpa_commit() { asm volatile("cp.async.commit_group;"); }
template <int N> __device__ __forceinline__ void cpa_wait() {
    asm volatile("cp.async.wait_group %0;" :: "n"(N));
}

// ---------------- prep: transposes + bf16 operand builds ----------------
#define XT_BLOCKS ((QTOT / 32) * (BATCH / 32))   // 9216
#define WT_BLOCKS 720
#define PX_BLOCKS 2304                            // 2304*2048 = 576*1024*8 u32
#define PW_BLOCKS 360                             // 360*2048 = 576*160*8 u32
__global__ void prep(const float* __restrict__ x, const float* __restrict__ W)
{
    if (blockIdx.x < XT_BLOCKS) {
        __shared__ float t[32][33];
        const int tile = blockIdx.x;
        const int q0 = (tile % (QTOT / 32)) * 32;
        const int b0 = (tile / (QTOT / 32)) * 32;
        const int lane = threadIdx.x & 31;
        const int w = threadIdx.x >> 5;
#pragma unroll
        for (int r = w; r < 32; r += 8)
            t[r][lane] = x[(size_t)(b0 + r) * QTOT + q0 + lane];
        __syncthreads();
#pragma unroll
        for (int r = w; r < 32; r += 8)
            g_xt[q0 + r][b0 + lane] = t[lane][r];
    } else if (blockIdx.x < XT_BLOCKS + WT_BLOCKS) {
        const int wb = blockIdx.x - XT_BLOCKS;
#pragma unroll
        for (int k = 0; k < 8; k++) {
            const int g = wb * 2048 + k * 256 + threadIdx.x;
            const int d = g & 15;
            const int e = (g >> 4) & 7;
            const int in = g >> 7;
            g_Wt[g] = W[(size_t)in * 128 + d * 8 + e];
        }
    } else if (blockIdx.x < XT_BLOCKS + WT_BLOCKS + PX_BLOCKS) {
        const int pb = blockIdx.x - XT_BLOCKS - WT_BLOCKS;
#pragma unroll
        for (int k = 0; k < 8; k++) {
            const int g = pb * 2048 + k * 256 + threadIdx.x;
            const int slab = g >> 13;
            const int r = g & 8191;
            const int b = r >> 3;
            const int q = r & 7;
            const int i = slab * 2 + (q & 1);
            const int e = (q >> 1) * 2;
            const float2 v = *reinterpret_cast<const float2*>(x + (size_t)b * QTOT + i * 8 + e);
            __nv_bfloat162 h = __float22bfloat162_rn(v);
            g_xpair[g] = *reinterpret_cast<uint32_t*>(&h);
        }
    } else {
        const int pb = blockIdx.x - XT_BLOCKS - WT_BLOCKS - PX_BLOCKS;
#pragma unroll
        for (int k = 0; k < 8; k++) {
            const int g = pb * 2048 + k * 256 + threadIdx.x;
            const int slab = g / 1280;
            const int r = g % 1280;
            const int nd = r >> 3;
            const int q = r & 7;
            const int n = nd >> 4, d = nd & 15;
            const int i = slab * 2 + (q & 1);
            const int e = (q >> 1) * 2;
            const float2 v = *reinterpret_cast<const float2*>(
                W + (((size_t)i * NOUT + n) * DOUT + d) * DIN + e);
            __nv_bfloat162 h = __float22bfloat162_rn(v);
            g_Wbf[g] = *reinterpret_cast<uint32_t*>(&h);
        }
    }
}

// ---------------- pass 0 (uniform weights) = bf16 GEMM via mma.sync ----------------
// D[b, n*16+d] = sum_K x[b,K] * W[K, n*16+d];  M=1024, N=160, K=9216.
// Grid (36 K-chunks, 16 M-tiles of 64). Warp w handles rows [b0+16w, b0+16w+16),
// 20 n8-tiles, 16 k16 steps. Accumulators in registers; writes g_partial[chunk].
__device__ __forceinline__ void hmma16816(float* c, uint32_t a0, uint32_t a1,
                                          uint32_t a2, uint32_t a3,
                                          uint32_t b0, uint32_t b1) {
    asm volatile(
        "mma.sync.aligned.m16n8k16.row.col.f32.bf16.bf16.f32 "
        "{%0,%1,%2,%3}, {%4,%5,%6,%7}, {%8,%9}, {%0,%1,%2,%3};"
        : "+f"(c[0]), "+f"(c[1]), "+f"(c[2]), "+f"(c[3])
        : "r"(a0), "r"(a1), "r"(a2), "r"(a3), "r"(b0), "r"(b1));
}

__global__ void __launch_bounds__(128) gemm_pass0()
{
    const int warp = threadIdx.x >> 5;
    const int lane = threadIdx.x & 31;
    const int gid = lane >> 2;        // 0..7
    const int tig = lane & 3;         // 0..3
    const int chunk = blockIdx.x;
    const int brow = blockIdx.y * 64 + warp * 16;
    const int slab0 = chunk * 16;

    float acc[20][4];
#pragma unroll
    for (int t = 0; t < 20; t++)
#pragma unroll
        for (int k = 0; k < 4; k++) acc[t][k] = 0.0f;

    for (int s = 0; s < 16; s++) {
        const uint32_t* __restrict__ xa =
            g_xpair + ((size_t)(slab0 + s) * BATCH + brow) * 8;
        // A fragment: rows gid / gid+8, k-pairs (2tig, 2tig+1) and (+8)
        const uint2 alo = *reinterpret_cast<const uint2*>(xa + gid * 8 + tig * 2);
        const uint2 ahi = *reinterpret_cast<const uint2*>(xa + (gid + 8) * 8 + tig * 2);
        const uint32_t a0 = alo.x, a2 = alo.y, a1 = ahi.x, a3 = ahi.y;

        const uint32_t* __restrict__ wb = g_Wbf + (size_t)(slab0 + s) * 160 * 8;
#pragma unroll
        for (int t = 0; t < 20; t++) {
            const uint2 bb = *reinterpret_cast<const uint2*>(wb + (t * 8 + gid) * 8 + tig * 2);
            hmma16816(acc[t], a0, a1, a2, a3, bb.x, bb.y);
        }
    }

    // epilogue: c0,c1 = (row gid, cols nd, nd+1); c2,c3 = (row gid+8, same cols)
    float* base0 = &g_partial[chunk][brow + gid][0][0];
    float* base1 = &g_partial[chunk][brow + gid + 8][0][0];
#pragma unroll
    for (int t = 0; t < 20; t++) {
        const int nd = t * 8 + tig * 2;
        *reinterpret_cast<float2*>(base0 + nd) = make_float2(acc[t][0], acc[t][1]);
        *reinterpret_cast<float2*>(base1 + nd) = make_float2(acc[t][2], acc[t][3]);
    }
}

// ---------------- passes 1-2: R6 scalar streaming route (best scalar) ----------------
__global__ void __launch_bounds__(320, 2)
route_pass()
{
    extern __shared__ float sm[];
    float* ws0 = sm;
    float* xs  = sm + 2 * WS_FLOATS;

    const int tid  = threadIdx.x;
    const int n    = tid >> 5;
    const int lane = tid & 31;
    const int dh   = lane >> 4;
    const int bl   = lane & 15;
    const int bA   = blockIdx.y * TB + bl;
    const int bB   = bA + 16;
    const int i0   = blockIdx.x * CI;

    {
        const float* src0 = &g_xt[i0 * DIN][0] + blockIdx.y * TB;
#pragma unroll
        for (int k = 0; k < 7; k++) {
            const int idx = tid + k * 320;
            if (idx < (CI * DIN) * (TB / 4)) {
                const int row = idx >> 3, off = idx & 7;
                cpa16(xs + row * TB + off * 4, src0 + (size_t)row * BATCH + off * 4);
            }
        }
    }
    const float* __restrict__ wbase = g_Wt + (size_t)i0 * NOUT * 128;
#pragma unroll
    for (int k = 0; k < 4; k++)
        cpa16(ws0 + (tid + k * 320) * 4, wbase + (size_t)(tid + k * 320) * 4);
    cpa_commit();

    u64 vsA[4], vsB[4];
    {
        const ulonglong2* vpA = reinterpret_cast<const ulonglong2*>(&g_vsum[bA][n][dh * 8]);
        const ulonglong2* vpB = reinterpret_cast<const ulonglong2*>(&g_vsum[bB][n][dh * 8]);
        ulonglong2 tA0 = vpA[0], tA1 = vpA[1];
        ulonglong2 tB0 = vpB[0], tB1 = vpB[1];
        vsA[0] = tA0.x; vsA[1] = tA0.y; vsA[2] = tA1.x; vsA[3] = tA1.y;
        vsB[0] = tB0.x; vsB[1] = tB0.y; vsB[2] = tB1.x; vsB[3] = tB1.y;
    }

    u64 accA[4], accB[4];
#pragma unroll
    for (int k = 0; k < 4; k++) { accA[k] = 0ull; accB[k] = 0ull; }
    float accdA = 0.0f, accdB = 0.0f;

    for (int s = 0; s < NSUB; s++) {
        if (s + 1 < NSUB) {
            float* dstw = ws0 + ((s + 1) & 1) * WS_FLOATS;
            const float* srcw = wbase + (size_t)(s + 1) * WS_FLOATS;
#pragma unroll
            for (int k = 0; k < 4; k++)
                cpa16(dstw + (tid + k * 320) * 4, srcw + (size_t)(tid + k * 320) * 4);
            cpa_commit();
            cpa_wait<1>();
        } else {
            cpa_wait<0>();
        }
        __syncthreads();

        const float* __restrict__ wsb = ws0 + (s & 1) * WS_FLOATS;
        const float* __restrict__ xsb = xs + s * SI * DIN * TB;

        for (int ii = 0; ii < SI; ii++) {
            const float* __restrict__ wp = wsb + (ii * NOUT + n) * 128 + dh * 8;

            u64 uA[4], uB[4];
#pragma unroll
            for (int e = 0; e < 8; e++) {
                const float xa = xsb[(ii * DIN + e) * TB + bl];
                const float xb = xsb[(ii * DIN + e) * TB + bl + 16];
                const u64 xdA = dup2(xa);
                const u64 xdB = dup2(xb);
                const ulonglong2 w01 = *reinterpret_cast<const ulonglong2*>(wp + e * 16);
                const ulonglong2 w23 = *reinterpret_cast<const ulonglong2*>(wp + e * 16 + 4);
                if (e == 0) {
                    uA[0] = mul2(xdA, w01.x); uA[1] = mul2(xdA, w01.y);
                    uA[2] = mul2(xdA, w23.x); uA[3] = mul2(xdA, w23.y);
                    uB[0] = mul2(xdB, w01.x); uB[1] = mul2(xdB, w01.y);
                    uB[2] = mul2(xdB, w23.x); uB[3] = mul2(xdB, w23.y);
                } else {
                    uA[0] = fma2(xdA, w01.x, uA[0]); uA[1] = fma2(xdA, w01.y, uA[1]);
                    uA[2] = fma2(xdA, w23.x, uA[2]); uA[3] = fma2(xdA, w23.y, uA[3]);
                    uB[0] = fma2(xdB, w01.x, uB[0]); uB[1] = fma2(xdB, w01.y, uB[1]);
                    uB[2] = fma2(xdB, w23.x, uB[2]); uB[3] = fma2(xdB, w23.y, uB[3]);
                }
            }

            u64 lA2 = mul2(uA[0], vsA[0]);
            u64 lB2 = mul2(uB[0], vsB[0]);
#pragma unroll
            for (int k = 1; k < 4; k++) {
                lA2 = fma2(uA[k], vsA[k], lA2);
                lB2 = fma2(uB[k], vsB[k], lB2);
            }
            float lA = hadd2(lA2);
            float lB = hadd2(lB2);
            lA += __shfl_xor_sync(0xffffffffu, lA, 16);
            lB += __shfl_xor_sync(0xffffffffu, lB, 16);
            const float wA = __expf(lA);    // logits O(10): no max-shift needed
            const float wB = __expf(lB);
            const u64 wdA = dup2(wA);
            const u64 wdB = dup2(wB);
#pragma unroll
            for (int k = 0; k < 4; k++) {
                accA[k] = fma2(wdA, uA[k], accA[k]);
                accB[k] = fma2(wdB, uB[k], accB[k]);
            }
            accdA += wA;
            accdB += wB;
        }
        __syncthreads();
    }

    ulonglong2* ppA = reinterpret_cast<ulonglong2*>(&g_partial[blockIdx.x][bA][n][dh * 8]);
    ppA[0] = make_ulonglong2(accA[0], accA[1]);
    ppA[1] = make_ulonglong2(accA[2], accA[3]);
    ulonglong2* ppB = reinterpret_cast<ulonglong2*>(&g_partial[blockIdx.x][bB][n][dh * 8]);
    ppB[0] = make_ulonglong2(accB[0], accB[1]);
    ppB[1] = make_ulonglong2(accB[2], accB[3]);
    if (dh == 0) {
        g_pden[blockIdx.x][bA][n] = accdA;
        g_pden[blockIdx.x][bB][n] = accdB;
    }
}

// ---------------- squash / vsum update ----------------
template <bool FIRST, bool LAST>
__global__ void __launch_bounds__(NOUT * DOUT)
squash_update(float* __restrict__ out)
{
    const int b = blockIdx.x;
    const int tid = threadIdx.x;
    const int n = tid >> 4;
    const int d = tid & 15;

    float num = 0.0f;
#pragma unroll
    for (int c = 0; c < NCHUNK; c++) num += g_partial[c][b][n][d];

    float den;
    if (FIRST) {
        den = (float)NIN;
    } else {
        den = 0.0f;
#pragma unroll
        for (int c = 0; c < NCHUNK; c++) den += g_pden[c][b][n];
    }

    const float s = num / den;

    float s2 = s * s;
#pragma unroll
    for (int off = 8; off; off >>= 1) s2 += __shfl_xor_sync(0xffffffffu, s2, off);

    const float scale = s2 / (1.0f + s2) * rsqrtf(s2 + 1e-7f);
    const float v = scale * s;

    if (LAST)       out[((size_t)b * NOUT + n) * DOUT + d] = v;
    else if (FIRST) g_vsum[b][n][d] = v;
    else            g_vsum[b][n][d] += v;
}

extern "C" void kernel_launch(void* const* d_in, const int* in_sizes, int n_in,
                              void* d_out, int out_size)
{
    const float* x;
    const float* W;
    if (in_sizes[0] == BATCH * NIN * DIN) { x = (const float*)d_in[0]; W = (const float*)d_in[1]; }
    else                                  { x = (const float*)d_in[1]; W = (const float*)d_in[0]; }
    float* out = (float*)d_out;

    static bool attr_done = false;
    if (!attr_done) {
        cudaFuncSetAttribute(route_pass, cudaFuncAttributeMaxDynamicSharedMemorySize, SMEM_BYTES);
        attr_done = true;
    }

    prep<<<XT_BLOCKS + WT_BLOCKS + PX_BLOCKS + PW_BLOCKS, 256>>>(x, W);

    // pass 0: tensor-core GEMM (uniform weights), K split across 36 chunks
    gemm_pass0<<<dim3(NCHUNK, BATCH / 64), 128>>>();
    squash_update<true , false><<<BATCH, NOUT * DOUT>>>(out);

    dim3 grid(NCHUNK, BTILES);
    route_pass<<<grid, 320, SMEM_BYTES>>>();
    squash_update<false, false><<<BATCH, NOUT * DOUT>>>(out);

    route_pass<<<grid, 320, SMEM_BYTES>>>();   // <- ncu capture slot (launch #6)
    squash_update<false, true ><<<BATCH, NOUT * DOUT>>>(out);
}

// round 10
// speedup vs baseline: 1.4105x; 1.0994x over previous
#include <cuda_runtime.h>
#include <cuda_bf16.h>
#include <cstdint>

#define BATCH 1024
#define NIN   1152
#define DIN   8
#define NOUT  10
#define DOUT  16
#define QTOT  (NIN * DIN)        // 9216
#define NCHUNK 36
#define CI     (NIN / NCHUNK)    // 32 i per chunk

// ---------------- static device scratch ----------------
__device__ float g_partial[NCHUNK][BATCH][NOUT][DOUT];
__device__ float g_pden[NCHUNK][BATCH][NOUT];
__device__ float g_vsum[BATCH][NOUT][DOUT];
// pass-0 GEMM operands (k16, 2 i per slab) — proven in R9
#define GSLABS_TOT (NIN / 2)
__device__ uint32_t g_xpair[GSLABS_TOT * BATCH * 8];
__device__ uint32_t g_Wbf[GSLABS_TOT * 160 * 8];
// passes 1-2 fragment-packed bf16x2 operands (hi/lo split), m16n8k8 order
// Wmma[(i*10+n)*128 + lane*4 + j]: j0=a0h(d=gid) j1=a1h(d=gid+8) j2=a0l j3=a1l; e=2tig
__device__ uint32_t g_Wmma[NIN * NOUT * 128];            // 5.9 MB
// xmma[((i*64)+btile)*128 + lane*4 + j]: j0=hi b=bt*16+gid, j1=hi b=+8, j2/j3=lo; e=2tig
__device__ uint32_t g_xmma[NIN * 64 * 128];              // 37.7 MB

// ---------------- cp.async ----------------
__device__ __forceinline__ void cpa16(void* smem_dst, const void* gmem_src) {
    unsigned s = (unsigned)__cvta_generic_to_shared(smem_dst);
    asm volatile("cp.async.cg.shared.global [%0], [%1], 16;" :: "r"(s), "l"(gmem_src));
}
__device__ __forceinline__ void cpa_commit() { asm volatile("cp.async.commit_group;"); }
template <int N> __device__ __forceinline__ void cpa_wait() {
    asm volatile("cp.async.wait_group %0;" :: "n"(N));
}

// ---------------- mma helpers ----------------
__device__ __forceinline__ void hmma16816(float* c, uint32_t a0, uint32_t a1,
                                          uint32_t a2, uint32_t a3,
                                          uint32_t b0, uint32_t b1) {
    asm volatile(
        "mma.sync.aligned.m16n8k16.row.col.f32.bf16.bf16.f32 "
        "{%0,%1,%2,%3}, {%4,%5,%6,%7}, {%8,%9}, {%0,%1,%2,%3};"
        : "+f"(c[0]), "+f"(c[1]), "+f"(c[2]), "+f"(c[3])
        : "r"(a0), "r"(a1), "r"(a2), "r"(a3), "r"(b0), "r"(b1));
}
__device__ __forceinline__ void hmma1688(float* c, uint32_t a0, uint32_t a1, uint32_t b0) {
    asm volatile(
        "mma.sync.aligned.m16n8k8.row.col.f32.bf16.bf16.f32 "
        "{%0,%1,%2,%3}, {%4,%5}, {%6}, {%0,%1,%2,%3};"
        : "+f"(c[0]), "+f"(c[1]), "+f"(c[2]), "+f"(c[3])
        : "r"(a0), "r"(a1), "r"(b0));
}

__device__ __forceinline__ uint32_t pack_bf16(float f0, float f1) {
    __nv_bfloat162 h = __float22bfloat162_rn(make_float2(f0, f1));
    return *reinterpret_cast<uint32_t*>(&h);
}
__device__ __forceinline__ uint32_t pack_bf16_lo(float f0, float f1) {
    float h0 = __bfloat162float(__float2bfloat16_rn(f0));
    float h1 = __bfloat162float(__float2bfloat16_rn(f1));
    return pack_bf16(f0 - h0, f1 - h1);
}

// ---------------- prep ----------------
#define WM_BLOCKS 720     // Wmma: 1,474,560 u32
#define XM_BLOCKS 4608    // xmma: 9,437,184 u32
#define PX_BLOCKS 2304    // xpair
#define PW_BLOCKS 360     // Wbf
__global__ void prep(const float* __restrict__ x, const float* __restrict__ W)
{
    if (blockIdx.x < WM_BLOCKS) {
#pragma unroll
        for (int k = 0; k < 8; k++) {
            const int g = blockIdx.x * 2048 + k * 256 + threadIdx.x;
            const int j = g & 3;
            const int lane = (g >> 2) & 31;
            const int in = g >> 7;                  // i*10+n
            const int gid = lane >> 2, tig = lane & 3;
            const int d = gid + ((j & 1) << 3);
            const int split = j >> 1;
            const float* src = W + ((size_t)in * 16 + d) * 8 + tig * 2;
            g_Wmma[g] = split ? pack_bf16_lo(src[0], src[1]) : pack_bf16(src[0], src[1]);
        }
    } else if (blockIdx.x < WM_BLOCKS + XM_BLOCKS) {
        const int xb = blockIdx.x - WM_BLOCKS;
#pragma unroll
        for (int k = 0; k < 8; k++) {
            const int g = xb * 2048 + k * 256 + threadIdx.x;
            const int j = g & 3;
            const int lane = (g >> 2) & 31;
            const int rest = g >> 7;
            const int t = rest & 63;                // batch tile
            const int i = rest >> 6;
            const int gid = lane >> 2, tig = lane & 3;
            const int b = t * 16 + ((j & 1) << 3) + gid;
            const int split = j >> 1;
            const float* src = x + (size_t)b * QTOT + i * 8 + tig * 2;
            g_xmma[g] = split ? pack_bf16_lo(src[0], src[1]) : pack_bf16(src[0], src[1]);
        }
    } else if (blockIdx.x < WM_BLOCKS + XM_BLOCKS + PX_BLOCKS) {
        const int pb = blockIdx.x - WM_BLOCKS - XM_BLOCKS;
#pragma unroll
        for (int k = 0; k < 8; k++) {
            const int g = pb * 2048 + k * 256 + threadIdx.x;
            const int slab = g >> 13;
            const int r = g & 8191;
            const int b = r >> 3;
            const int q = r & 7;
            const int i = slab * 2 + (q & 1);
            const int e = (q >> 1) * 2;
            const float* src = x + (size_t)b * QTOT + i * 8 + e;
            g_xpair[g] = pack_bf16(src[0], src[1]);
        }
    } else {
        const int pb = blockIdx.x - WM_BLOCKS - XM_BLOCKS - PX_BLOCKS;
#pragma unroll
        for (int k = 0; k < 8; k++) {
            const int g = pb * 2048 + k * 256 + threadIdx.x;
            const int slab = g / 1280;
            const int r = g % 1280;
            const int nd = r >> 3;
            const int q = r & 7;
            const int n = nd >> 4, d = nd & 15;
            const int i = slab * 2 + (q & 1);
            const int e = (q >> 1) * 2;
            const float* src = W + (((size_t)i * NOUT + n) * DOUT + d) * DIN + e;
            g_Wbf[g] = pack_bf16(src[0], src[1]);
        }
    }
}

// ---------------- pass 0 (uniform weights) — proven R9 GEMM ----------------
__global__ void __launch_bounds__(128) gemm_pass0()
{
    const int warp = threadIdx.x >> 5;
    const int lane = threadIdx.x & 31;
    const int gid = lane >> 2;
    const int tig = lane & 3;
    const int chunk = blockIdx.x;
    const int brow = blockIdx.y * 64 + warp * 16;
    const int slab0 = chunk * 16;

    float acc[20][4];
#pragma unroll
    for (int t = 0; t < 20; t++)
#pragma unroll
        for (int k = 0; k < 4; k++) acc[t][k] = 0.0f;

    for (int s = 0; s < 16; s++) {
        const uint32_t* __restrict__ xa =
            g_xpair + ((size_t)(slab0 + s) * BATCH + brow) * 8;
        const uint2 alo = *reinterpret_cast<const uint2*>(xa + gid * 8 + tig * 2);
        const uint2 ahi = *reinterpret_cast<const uint2*>(xa + (gid + 8) * 8 + tig * 2);
        const uint32_t a0 = alo.x, a2 = alo.y, a1 = ahi.x, a3 = ahi.y;

        const uint32_t* __restrict__ wb = g_Wbf + (size_t)(slab0 + s) * 160 * 8;
#pragma unroll
        for (int t = 0; t < 20; t++) {
            const uint2 bb = *reinterpret_cast<const uint2*>(wb + (t * 8 + gid) * 8 + tig * 2);
            hmma16816(acc[t], a0, a1, a2, a3, bb.x, bb.y);
        }
    }

    float* base0 = &g_partial[chunk][brow + gid][0][0];
    float* base1 = &g_partial[chunk][brow + gid + 8][0][0];
#pragma unroll
    for (int t = 0; t < 20; t++) {
        const int nd = t * 8 + tig * 2;
        *reinterpret_cast<float2*>(base0 + nd) = make_float2(acc[t][0], acc[t][1]);
        *reinterpret_cast<float2*>(base1 + nd) = make_float2(acc[t][2], acc[t][3]);
    }
}

// ---------------- passes 1-2: tensor-core fused routing pass ----------------
// warp = n. Per i: u_hat[16d x 16b] via 6x m16n8k8 (bf16x3: hh + hl + lh),
// logit dot vs Vsum (regs), gid-reduce via shfl, exp, s += w*u in fp32 regs.
#define RSI 4
#define RNSUB (CI / RSI)                 // 8
#define RW_U32 (RSI * NOUT * 128)        // 5120 u32 = 20KB per buffer
#define RX_U32 (CI * 128)                // 4096 u32 = 16KB
#define RSMEM ((2 * RW_U32 + RX_U32) * 4)  // 56KB

__global__ void __launch_bounds__(320, 2) route_pass()
{
    extern __shared__ uint32_t smr[];
    uint32_t* ws  = smr;                  // [2][RW_U32]
    uint32_t* xsm = smr + 2 * RW_U32;     // [CI][128]

    const int tid  = threadIdx.x;
    const int n    = tid >> 5;
    const int lane = tid & 31;
    const int gid  = lane >> 2;
    const int tig  = lane & 3;
    const int chunk = blockIdx.x;
    const int i0    = chunk * CI;
    const int b0    = blockIdx.y * 16;

    // stage x tile (1024 uint4)
#pragma unroll
    for (int k = 0; k < 4; k++) {
        const int idx = tid + k * 320;
        if (idx < 1024) {
            const int il = idx >> 5, off = idx & 31;
            cpa16(xsm + il * 128 + off * 4,
                  g_xmma + ((size_t)(i0 + il) * 64 + blockIdx.y) * 128 + off * 4);
        }
    }
    // stage W sub-tile 0 (1280 uint4)
    const uint32_t* __restrict__ wsrc = g_Wmma + (size_t)i0 * NOUT * 128;
#pragma unroll
    for (int k = 0; k < 4; k++) {
        const int idx = tid + k * 320;
        cpa16(ws + idx * 4, wsrc + (size_t)idx * 4);
    }
    cpa_commit();

    // Vsum registers for this thread's (b, d) ownership
    int bcol[4];
    bcol[0] = b0 + 2 * tig;     bcol[1] = bcol[0] + 1;
    bcol[2] = bcol[0] + 8;      bcol[3] = bcol[0] + 9;
    float V[4][2];
#pragma unroll
    for (int j = 0; j < 4; j++) {
        V[j][0] = g_vsum[bcol[j]][n][gid];
        V[j][1] = g_vsum[bcol[j]][n][gid + 8];
    }

    float s0[4] = {0, 0, 0, 0}, s1[4] = {0, 0, 0, 0};
    float den[4] = {0, 0, 0, 0};

    for (int s = 0; s < RNSUB; s++) {
        if (s + 1 < RNSUB) {
            uint32_t* dst = ws + ((s + 1) & 1) * RW_U32;
            const uint32_t* src = wsrc + (size_t)(s + 1) * RW_U32;
#pragma unroll
            for (int k = 0; k < 4; k++) {
                const int idx = tid + k * 320;
                cpa16(dst + idx * 4, src + (size_t)idx * 4);
            }
            cpa_commit();
            cpa_wait<1>();
        } else {
            cpa_wait<0>();
        }
        __syncthreads();

        const uint32_t* __restrict__ wsb = ws + (s & 1) * RW_U32;
#pragma unroll 2
        for (int ii = 0; ii < RSI; ii++) {
            const uint4 A = *reinterpret_cast<const uint4*>(wsb + (ii * NOUT + n) * 128 + lane * 4);
            const uint4 B = *reinterpret_cast<const uint4*>(xsm + (s * RSI + ii) * 128 + lane * 4);

            float u0[4] = {0, 0, 0, 0}, u1[4] = {0, 0, 0, 0};
            hmma1688(u0, A.x, A.y, B.x);   // hi*hi, b-tile 0
            hmma1688(u0, A.x, A.y, B.z);   // hi*lo
            hmma1688(u0, A.z, A.w, B.x);   // lo*hi
            hmma1688(u1, A.x, A.y, B.y);   // hi*hi, b-tile 1
            hmma1688(u1, A.x, A.y, B.w);   // hi*lo
            hmma1688(u1, A.z, A.w, B.y);   // lo*hi

            // logit partials (d = gid, gid+8 in-thread)
            float p[4];
            p[0] = u0[0] * V[0][0] + u0[2] * V[0][1];
            p[1] = u0[1] * V[1][0] + u0[3] * V[1][1];
            p[2] = u1[0] * V[2][0] + u1[2] * V[2][1];
            p[3] = u1[1] * V[3][0] + u1[3] * V[3][1];
            // reduce over gid (lane bits 2..4)
#pragma unroll
            for (int m = 4; m <= 16; m <<= 1) {
#pragma unroll
                for (int j = 0; j < 4; j++)
                    p[j] += __shfl_xor_sync(0xffffffffu, p[j], m);
            }
            float w[4];
#pragma unroll
            for (int j = 0; j < 4; j++) w[j] = __expf(p[j]);   // logits O(10): no shift

            s0[0] += w[0] * u0[0];  s0[2] += w[0] * u0[2];
            s0[1] += w[1] * u0[1];  s0[3] += w[1] * u0[3];
            s1[0] += w[2] * u1[0];  s1[2] += w[2] * u1[2];
            s1[1] += w[3] * u1[1];  s1[3] += w[3] * u1[3];
#pragma unroll
            for (int j = 0; j < 4; j++) den[j] += w[j];
        }
        __syncthreads();
    }

    g_partial[chunk][bcol[0]][n][gid]     = s0[0];
    g_partial[chunk][bcol[0]][n][gid + 8] = s0[2];
    g_partial[chunk][bcol[1]][n][gid]     = s0[1];
    g_partial[chunk][bcol[1]][n][gid + 8] = s0[3];
    g_partial[chunk][bcol[2]][n][gid]     = s1[0];
    g_partial[chunk][bcol[2]][n][gid + 8] = s1[2];
    g_partial[chunk][bcol[3]][n][gid]     = s1[1];
    g_partial[chunk][bcol[3]][n][gid + 8] = s1[3];
    if (gid == 0) {
#pragma unroll
        for (int j = 0; j < 4; j++) g_pden[chunk][bcol[j]][n] = den[j];
    }
}

// ---------------- squash / vsum update ----------------
template <bool FIRST, bool LAST>
__global__ void __launch_bounds__(NOUT * DOUT)
squash_update(float* __restrict__ out)
{
    const int b = blockIdx.x;
    const int tid = threadIdx.x;
    const int n = tid >> 4;
    const int d = tid & 15;

    float num = 0.0f;
#pragma unroll
    for (int c = 0; c < NCHUNK; c++) num += g_partial[c][b][n][d];

    float den;
    if (FIRST) {
        den = (float)NIN;
    } else {
        den = 0.0f;
#pragma unroll
        for (int c = 0; c < NCHUNK; c++) den += g_pden[c][b][n];
    }

    const float s = num / den;

    float s2 = s * s;
#pragma unroll
    for (int off = 8; off; off >>= 1) s2 += __shfl_xor_sync(0xffffffffu, s2, off);

    const float scale = s2 / (1.0f + s2) * rsqrtf(s2 + 1e-7f);
    const float v = scale * s;

    if (LAST)       out[((size_t)b * NOUT + n) * DOUT + d] = v;
    else if (FIRST) g_vsum[b][n][d] = v;
    else            g_vsum[b][n][d] += v;
}

extern "C" void kernel_launch(void* const* d_in, const int* in_sizes, int n_in,
                              void* d_out, int out_size)
{
    const float* x;
    const float* W;
    if (in_sizes[0] == BATCH * NIN * DIN) { x = (const float*)d_in[0]; W = (const float*)d_in[1]; }
    else                                  { x = (const float*)d_in[1]; W = (const float*)d_in[0]; }
    float* out = (float*)d_out;

    static bool attr_done = false;
    if (!attr_done) {
        cudaFuncSetAttribute(route_pass, cudaFuncAttributeMaxDynamicSharedMemorySize, RSMEM);
        attr_done = true;
    }

    prep<<<WM_BLOCKS + XM_BLOCKS + PX_BLOCKS + PW_BLOCKS, 256>>>(x, W);

    gemm_pass0<<<dim3(NCHUNK, BATCH / 64), 128>>>();
    squash_update<true , false><<<BATCH, NOUT * DOUT>>>(out);

    route_pass<<<dim3(NCHUNK, BATCH / 16), 320, RSMEM>>>();
    squash_update<false, false><<<BATCH, NOUT * DOUT>>>(out);

    route_pass<<<dim3(NCHUNK, BATCH / 16), 320, RSMEM>>>();   // <- ncu capture slot
    squash_update<false, true ><<<BATCH, NOUT * DOUT>>>(out);
}

// round 11
// speedup vs baseline: 1.4592x; 1.0345x over previous
#include <cuda_runtime.h>
#include <cuda_bf16.h>
#include <cstdint>

#define BATCH 1024
#define NIN   1152
#define DIN   8
#define NOUT  10
#define DOUT  16
#define QTOT  (NIN * DIN)        // 9216
#define NCHUNK 36
#define CI     (NIN / NCHUNK)    // 32 i per chunk

// ---------------- static device scratch ----------------
__device__ float g_partial[NCHUNK][BATCH][NOUT][DOUT];
__device__ float g_pden[NCHUNK][BATCH][NOUT];
__device__ float g_vsum[BATCH][NOUT][DOUT];
// pass-0 GEMM operands (k16, 2 i per slab) — proven R9
#define GSLABS_TOT (NIN / 2)
__device__ uint32_t g_xpair[GSLABS_TOT * BATCH * 8];
__device__ uint32_t g_Wbf[GSLABS_TOT * 160 * 8];
// passes 1-2 fragment-packed bf16x2 operands (hi/lo split), m16n8k8 order
__device__ uint32_t g_Wmma[NIN * NOUT * 128];            // 5.9 MB
__device__ uint32_t g_xmma[NIN * 64 * 128];              // 37.7 MB

// ---------------- cp.async ----------------
__device__ __forceinline__ void cpa16(void* smem_dst, const void* gmem_src) {
    unsigned s = (unsigned)__cvta_generic_to_shared(smem_dst);
    asm volatile("cp.async.cg.shared.global [%0], [%1], 16;" :: "r"(s), "l"(gmem_src));
}
__device__ __forceinline__ void cpa_commit() { asm volatile("cp.async.commit_group;"); }
template <int N> __device__ __forceinline__ void cpa_wait() {
    asm volatile("cp.async.wait_group %0;" :: "n"(N));
}

// ---------------- mma helpers ----------------
__device__ __forceinline__ void hmma16816(float* c, uint32_t a0, uint32_t a1,
                                          uint32_t a2, uint32_t a3,
                                          uint32_t b0, uint32_t b1) {
    asm volatile(
        "mma.sync.aligned.m16n8k16.row.col.f32.bf16.bf16.f32 "
        "{%0,%1,%2,%3}, {%4,%5,%6,%7}, {%8,%9}, {%0,%1,%2,%3};"
        : "+f"(c[0]), "+f"(c[1]), "+f"(c[2]), "+f"(c[3])
        : "r"(a0), "r"(a1), "r"(a2), "r"(a3), "r"(b0), "r"(b1));
}
__device__ __forceinline__ void hmma1688(float* c, uint32_t a0, uint32_t a1, uint32_t b0) {
    asm volatile(
        "mma.sync.aligned.m16n8k8.row.col.f32.bf16.bf16.f32 "
        "{%0,%1,%2,%3}, {%4,%5}, {%6}, {%0,%1,%2,%3};"
        : "+f"(c[0]), "+f"(c[1]), "+f"(c[2]), "+f"(c[3])
        : "r"(a0), "r"(a1), "r"(b0));
}
__device__ __forceinline__ float ex2f(float x) {
    float r; asm("ex2.approx.f32 %0, %1;" : "=f"(r) : "f"(x)); return r;
}

__device__ __forceinline__ uint32_t pack_bf16(float f0, float f1) {
    __nv_bfloat162 h = __float22bfloat162_rn(make_float2(f0, f1));
    return *reinterpret_cast<uint32_t*>(&h);
}
__device__ __forceinline__ uint32_t pack_bf16_lo(float f0, float f1) {
    float h0 = __bfloat162float(__float2bfloat16_rn(f0));
    float h1 = __bfloat162float(__float2bfloat16_rn(f1));
    return pack_bf16(f0 - h0, f1 - h1);
}

// ---------------- prep ----------------
#define WM_BLOCKS 720
#define XM_BLOCKS 4608
#define PX_BLOCKS 2304
#define PW_BLOCKS 360
__global__ void prep(const float* __restrict__ x, const float* __restrict__ W)
{
    if (blockIdx.x < WM_BLOCKS) {
#pragma unroll
        for (int k = 0; k < 8; k++) {
            const int g = blockIdx.x * 2048 + k * 256 + threadIdx.x;
            const int j = g & 3;
            const int lane = (g >> 2) & 31;
            const int in = g >> 7;
            const int gid = lane >> 2, tig = lane & 3;
            const int d = gid + ((j & 1) << 3);
            const int split = j >> 1;
            const float* src = W + ((size_t)in * 16 + d) * 8 + tig * 2;
            g_Wmma[g] = split ? pack_bf16_lo(src[0], src[1]) : pack_bf16(src[0], src[1]);
        }
    } else if (blockIdx.x < WM_BLOCKS + XM_BLOCKS) {
        const int xb = blockIdx.x - WM_BLOCKS;
#pragma unroll
        for (int k = 0; k < 8; k++) {
            const int g = xb * 2048 + k * 256 + threadIdx.x;
            const int j = g & 3;
            const int lane = (g >> 2) & 31;
            const int rest = g >> 7;
            const int t = rest & 63;
            const int i = rest >> 6;
            const int gid = lane >> 2, tig = lane & 3;
            const int b = t * 16 + ((j & 1) << 3) + gid;
            const int split = j >> 1;
            const float* src = x + (size_t)b * QTOT + i * 8 + tig * 2;
            g_xmma[g] = split ? pack_bf16_lo(src[0], src[1]) : pack_bf16(src[0], src[1]);
        }
    } else if (blockIdx.x < WM_BLOCKS + XM_BLOCKS + PX_BLOCKS) {
        const int pb = blockIdx.x - WM_BLOCKS - XM_BLOCKS;
#pragma unroll
        for (int k = 0; k < 8; k++) {
            const int g = pb * 2048 + k * 256 + threadIdx.x;
            const int slab = g >> 13;
            const int r = g & 8191;
            const int b = r >> 3;
            const int q = r & 7;
            const int i = slab * 2 + (q & 1);
            const int e = (q >> 1) * 2;
            const float* src = x + (size_t)b * QTOT + i * 8 + e;
            g_xpair[g] = pack_bf16(src[0], src[1]);
        }
    } else {
        const int pb = blockIdx.x - WM_BLOCKS - XM_BLOCKS - PX_BLOCKS;
#pragma unroll
        for (int k = 0; k < 8; k++) {
            const int g = pb * 2048 + k * 256 + threadIdx.x;
            const int slab = g / 1280;
            const int r = g % 1280;
            const int nd = r >> 3;
            const int q = r & 7;
            const int n = nd >> 4, d = nd & 15;
            const int i = slab * 2 + (q & 1);
            const int e = (q >> 1) * 2;
            const float* src = W + (((size_t)i * NOUT + n) * DOUT + d) * DIN + e;
            g_Wbf[g] = pack_bf16(src[0], src[1]);
        }
    }
}

// ---------------- pass 0 (uniform weights) — proven R9 GEMM ----------------
__global__ void __launch_bounds__(128) gemm_pass0()
{
    const int warp = threadIdx.x >> 5;
    const int lane = threadIdx.x & 31;
    const int gid = lane >> 2;
    const int tig = lane & 3;
    const int chunk = blockIdx.x;
    const int brow = blockIdx.y * 64 + warp * 16;
    const int slab0 = chunk * 16;

    float acc[20][4];
#pragma unroll
    for (int t = 0; t < 20; t++)
#pragma unroll
        for (int k = 0; k < 4; k++) acc[t][k] = 0.0f;

    for (int s = 0; s < 16; s++) {
        const uint32_t* __restrict__ xa =
            g_xpair + ((size_t)(slab0 + s) * BATCH + brow) * 8;
        const uint2 alo = *reinterpret_cast<const uint2*>(xa + gid * 8 + tig * 2);
        const uint2 ahi = *reinterpret_cast<const uint2*>(xa + (gid + 8) * 8 + tig * 2);
        const uint32_t a0 = alo.x, a2 = alo.y, a1 = ahi.x, a3 = ahi.y;

        const uint32_t* __restrict__ wb = g_Wbf + (size_t)(slab0 + s) * 160 * 8;
#pragma unroll
        for (int t = 0; t < 20; t++) {
            const uint2 bb = *reinterpret_cast<const uint2*>(wb + (t * 8 + gid) * 8 + tig * 2);
            hmma16816(acc[t], a0, a1, a2, a3, bb.x, bb.y);
        }
    }

    float* base0 = &g_partial[chunk][brow + gid][0][0];
    float* base1 = &g_partial[chunk][brow + gid + 8][0][0];
#pragma unroll
    for (int t = 0; t < 20; t++) {
        const int nd = t * 8 + tig * 2;
        *reinterpret_cast<float2*>(base0 + nd) = make_float2(acc[t][0], acc[t][1]);
        *reinterpret_cast<float2*>(base1 + nd) = make_float2(acc[t][2], acc[t][3]);
    }
}

// ---------------- passes 1-2: tensor-core fused routing pass ----------------
// PRECISE=false (pass 1): u in single bf16 (only steers vsum) -> 1 HMMA/b-tile.
// PRECISE=true  (pass 2): bf16x3 split (output-grade) -> 3 HMMA/b-tile.
#define RSI 2
#define RNSUB (CI / RSI)                 // 16
#define RW_U32 (RSI * NOUT * 128)        // 2560 u32 = 10KB per buffer
#define RX_U32 (CI * 128)                // 4096 u32 = 16KB
#define RSMEM ((2 * RW_U32 + RX_U32) * 4)  // 36KB

template <bool PRECISE>
__global__ void __launch_bounds__(320, 3) route_pass()
{
    extern __shared__ uint32_t smr[];
    uint32_t* ws  = smr;                  // [2][RW_U32]
    uint32_t* xsm = smr + 2 * RW_U32;     // [CI][128]

    const int tid  = threadIdx.x;
    const int n    = tid >> 5;
    const int lane = tid & 31;
    const int gid  = lane >> 2;
    const int tig  = lane & 3;
    const int chunk = blockIdx.x;
    const int i0    = chunk * CI;
    const int b0    = blockIdx.y * 16;

    // stage x tile (1024 uint4)
#pragma unroll
    for (int k = 0; k < 4; k++) {
        const int idx = tid + k * 320;
        if (idx < 1024) {
            const int il = idx >> 5, off = idx & 31;
            cpa16(xsm + il * 128 + off * 4,
                  g_xmma + ((size_t)(i0 + il) * 64 + blockIdx.y) * 128 + off * 4);
        }
    }
    // stage W sub-tile 0 (640 uint4)
    const uint32_t* __restrict__ wsrc = g_Wmma + (size_t)i0 * NOUT * 128;
#pragma unroll
    for (int k = 0; k < 2; k++) {
        const int idx = tid + k * 320;
        cpa16(ws + idx * 4, wsrc + (size_t)idx * 4);
    }
    cpa_commit();

    int bcol[4];
    bcol[0] = b0 + 2 * tig;     bcol[1] = bcol[0] + 1;
    bcol[2] = bcol[0] + 8;      bcol[3] = bcol[0] + 9;
    // V pre-scaled by log2(e): logit reduce lands in log2 domain -> ex2 directly
    float V[4][2];
#pragma unroll
    for (int j = 0; j < 4; j++) {
        V[j][0] = g_vsum[bcol[j]][n][gid]     * 1.4426950408889634f;
        V[j][1] = g_vsum[bcol[j]][n][gid + 8] * 1.4426950408889634f;
    }

    float s0[4] = {0, 0, 0, 0}, s1[4] = {0, 0, 0, 0};
    float den[4] = {0, 0, 0, 0};

    for (int s = 0; s < RNSUB; s++) {
        if (s + 1 < RNSUB) {
            uint32_t* dst = ws + ((s + 1) & 1) * RW_U32;
            const uint32_t* src = wsrc + (size_t)(s + 1) * RW_U32;
#pragma unroll
            for (int k = 0; k < 2; k++) {
                const int idx = tid + k * 320;
                cpa16(dst + idx * 4, src + (size_t)idx * 4);
            }
            cpa_commit();
            cpa_wait<1>();
        } else {
            cpa_wait<0>();
        }
        __syncthreads();

        const uint32_t* __restrict__ wsb = ws + (s & 1) * RW_U32;
#pragma unroll
        for (int ii = 0; ii < RSI; ii++) {
            float u0[4] = {0, 0, 0, 0}, u1[4] = {0, 0, 0, 0};
            if (PRECISE) {
                const uint4 A = *reinterpret_cast<const uint4*>(wsb + (ii * NOUT + n) * 128 + lane * 4);
                const uint4 B = *reinterpret_cast<const uint4*>(xsm + (s * RSI + ii) * 128 + lane * 4);
                hmma1688(u0, A.x, A.y, B.x);   // hi*hi, b-tile 0
                hmma1688(u0, A.x, A.y, B.z);   // hi*lo
                hmma1688(u0, A.z, A.w, B.x);   // lo*hi
                hmma1688(u1, A.x, A.y, B.y);   // hi*hi, b-tile 1
                hmma1688(u1, A.x, A.y, B.w);   // hi*lo
                hmma1688(u1, A.z, A.w, B.y);   // lo*hi
            } else {
                const uint2 A = *reinterpret_cast<const uint2*>(wsb + (ii * NOUT + n) * 128 + lane * 4);
                const uint2 B = *reinterpret_cast<const uint2*>(xsm + (s * RSI + ii) * 128 + lane * 4);
                hmma1688(u0, A.x, A.y, B.x);
                hmma1688(u1, A.x, A.y, B.y);
            }

            float p[4];
            p[0] = u0[0] * V[0][0] + u0[2] * V[0][1];
            p[1] = u0[1] * V[1][0] + u0[3] * V[1][1];
            p[2] = u1[0] * V[2][0] + u1[2] * V[2][1];
            p[3] = u1[1] * V[3][0] + u1[3] * V[3][1];
#pragma unroll
            for (int m = 4; m <= 16; m <<= 1) {
#pragma unroll
                for (int j = 0; j < 4; j++)
                    p[j] += __shfl_xor_sync(0xffffffffu, p[j], m);
            }
            float w[4];
#pragma unroll
            for (int j = 0; j < 4; j++) w[j] = ex2f(p[j]);   // logits O(10): no shift

            s0[0] += w[0] * u0[0];  s0[2] += w[0] * u0[2];
            s0[1] += w[1] * u0[1];  s0[3] += w[1] * u0[3];
            s1[0] += w[2] * u1[0];  s1[2] += w[2] * u1[2];
            s1[1] += w[3] * u1[1];  s1[3] += w[3] * u1[3];
#pragma unroll
            for (int j = 0; j < 4; j++) den[j] += w[j];
        }
        __syncthreads();
    }

    g_partial[chunk][bcol[0]][n][gid]     = s0[0];
    g_partial[chunk][bcol[0]][n][gid + 8] = s0[2];
    g_partial[chunk][bcol[1]][n][gid]     = s0[1];
    g_partial[chunk][bcol[1]][n][gid + 8] = s0[3];
    g_partial[chunk][bcol[2]][n][gid]     = s1[0];
    g_partial[chunk][bcol[2]][n][gid + 8] = s1[2];
    g_partial[chunk][bcol[3]][n][gid]     = s1[1];
    g_partial[chunk][bcol[3]][n][gid + 8] = s1[3];
    if (gid == 0) {
#pragma unroll
        for (int j = 0; j < 4; j++) g_pden[chunk][bcol[j]][n] = den[j];
    }
}

// ---------------- squash / vsum update ----------------
template <bool FIRST, bool LAST>
__global__ void __launch_bounds__(NOUT * DOUT)
squash_update(float* __restrict__ out)
{
    const int b = blockIdx.x;
    const int tid = threadIdx.x;
    const int n = tid >> 4;
    const int d = tid & 15;

    float num = 0.0f;
#pragma unroll
    for (int c = 0; c < NCHUNK; c++) num += g_partial[c][b][n][d];

    float den;
    if (FIRST) {
        den = (float)NIN;
    } else {
        den = 0.0f;
#pragma unroll
        for (int c = 0; c < NCHUNK; c++) den += g_pden[c][b][n];
    }

    const float s = num / den;

    float s2 = s * s;
#pragma unroll
    for (int off = 8; off; off >>= 1) s2 += __shfl_xor_sync(0xffffffffu, s2, off);

    const float scale = s2 / (1.0f + s2) * rsqrtf(s2 + 1e-7f);
    const float v = scale * s;

    if (LAST)       out[((size_t)b * NOUT + n) * DOUT + d] = v;
    else if (FIRST) g_vsum[b][n][d] = v;
    else            g_vsum[b][n][d] += v;
}

extern "C" void kernel_launch(void* const* d_in, const int* in_sizes, int n_in,
                              void* d_out, int out_size)
{
    const float* x;
    const float* W;
    if (in_sizes[0] == BATCH * NIN * DIN) { x = (const float*)d_in[0]; W = (const float*)d_in[1]; }
    else                                  { x = (const float*)d_in[1]; W = (const float*)d_in[0]; }
    float* out = (float*)d_out;

    prep<<<WM_BLOCKS + XM_BLOCKS + PX_BLOCKS + PW_BLOCKS, 256>>>(x, W);

    gemm_pass0<<<dim3(NCHUNK, BATCH / 64), 128>>>();
    squash_update<true , false><<<BATCH, NOUT * DOUT>>>(out);

    route_pass<false><<<dim3(NCHUNK, BATCH / 16), 320, RSMEM>>>();
    squash_update<false, false><<<BATCH, NOUT * DOUT>>>(out);

    route_pass<true ><<<dim3(NCHUNK, BATCH / 16), 320, RSMEM>>>();   // <- ncu capture slot
    squash_update<false, true ><<<BATCH, NOUT * DOUT>>>(out);
}

// round 12
// speedup vs baseline: 1.8238x; 1.2498x over previous
#include <cuda_runtime.h>
#include <cuda_bf16.h>
#include <cstdint>

#define BATCH 1024
#define NIN   1152
#define DIN   8
#define NOUT  10
#define DOUT  16
#define QTOT  (NIN * DIN)        // 9216
#define NCHUNK 36
#define CI     (NIN / NCHUNK)    // 32 i per chunk

// ---------------- static device scratch ----------------
__device__ float g_partial[NCHUNK][BATCH][NOUT][DOUT];
__device__ float g_pden[NCHUNK][BATCH][NOUT];
__device__ float g_vsum[BATCH][NOUT][DOUT];
// pass-0 GEMM operands (k16, 2 i per slab) — proven R9
#define GSLABS_TOT (NIN / 2)
__device__ uint32_t g_xpair[GSLABS_TOT * BATCH * 8];
__device__ uint32_t g_Wbf[GSLABS_TOT * 160 * 8];
// passes 1-2: m16n8k8 fragments, hi/lo SPLIT arrays.
// g_Wh[(i*10+n)*64 + lane*2 + r]: r0 = W[d=gid][e=2tig,2tig+1] hi-pair, r1 = d=gid+8
// g_xh[(i*64+t)*64 + lane*2 + r]: r0 = x[b=t*16+gid][i][e=2tig pair] hi, r1 = b+8
__device__ uint32_t g_Wh[NIN * NOUT * 64];
__device__ uint32_t g_Wl[NIN * NOUT * 64];
__device__ uint32_t g_xh[NIN * 64 * 64];
__device__ uint32_t g_xl[NIN * 64 * 64];

// ---------------- cp.async ----------------
__device__ __forceinline__ void cpa16(void* smem_dst, const void* gmem_src) {
    unsigned s = (unsigned)__cvta_generic_to_shared(smem_dst);
    asm volatile("cp.async.cg.shared.global [%0], [%1], 16;" :: "r"(s), "l"(gmem_src));
}
__device__ __forceinline__ void cpa_commit() { asm volatile("cp.async.commit_group;"); }
template <int N> __device__ __forceinline__ void cpa_wait() {
    asm volatile("cp.async.wait_group %0;" :: "n"(N));
}

// ---------------- mma helpers ----------------
__device__ __forceinline__ void hmma16816(float* c, uint32_t a0, uint32_t a1,
                                          uint32_t a2, uint32_t a3,
                                          uint32_t b0, uint32_t b1) {
    asm volatile(
        "mma.sync.aligned.m16n8k16.row.col.f32.bf16.bf16.f32 "
        "{%0,%1,%2,%3}, {%4,%5,%6,%7}, {%8,%9}, {%0,%1,%2,%3};"
        : "+f"(c[0]), "+f"(c[1]), "+f"(c[2]), "+f"(c[3])
        : "r"(a0), "r"(a1), "r"(a2), "r"(a3), "r"(b0), "r"(b1));
}
__device__ __forceinline__ void hmma1688(float* c, uint32_t a0, uint32_t a1, uint32_t b0) {
    asm volatile(
        "mma.sync.aligned.m16n8k8.row.col.f32.bf16.bf16.f32 "
        "{%0,%1,%2,%3}, {%4,%5}, {%6}, {%0,%1,%2,%3};"
        : "+f"(c[0]), "+f"(c[1]), "+f"(c[2]), "+f"(c[3])
        : "r"(a0), "r"(a1), "r"(b0));
}
__device__ __forceinline__ float ex2f(float x) {
    float r; asm("ex2.approx.f32 %0, %1;" : "=f"(r) : "f"(x)); return r;
}

__device__ __forceinline__ uint32_t pack_bf16(float f0, float f1) {
    __nv_bfloat162 h = __float22bfloat162_rn(make_float2(f0, f1));
    return *reinterpret_cast<uint32_t*>(&h);
}
__device__ __forceinline__ uint32_t pack_bf16_lo(float f0, float f1) {
    float h0 = __bfloat162float(__float2bfloat16_rn(f0));
    float h1 = __bfloat162float(__float2bfloat16_rn(f1));
    return pack_bf16(f0 - h0, f1 - h1);
}

// ---------------- prep ----------------
#define WH_BLOCKS 360     // 737,280 u32
#define WL_BLOCKS 360
#define XH_BLOCKS 2304    // 4,718,592 u32
#define XL_BLOCKS 2304
#define PX_BLOCKS 2304
#define PW_BLOCKS 360
__global__ void prep(const float* __restrict__ x, const float* __restrict__ W)
{
    const int blk = blockIdx.x;
    if (blk < WH_BLOCKS + WL_BLOCKS) {
        const bool lo = blk >= WH_BLOCKS;
        const int base = (lo ? blk - WH_BLOCKS : blk) * 2048;
#pragma unroll
        for (int k = 0; k < 8; k++) {
            const int g = base + k * 256 + threadIdx.x;
            const int r = g & 1;
            const int lane = (g >> 1) & 31;
            const int in = g >> 6;
            const int gid = lane >> 2, tig = lane & 3;
            const int d = gid + r * 8;
            const float* src = W + ((size_t)in * 16 + d) * 8 + tig * 2;
            (lo ? g_Wl : g_Wh)[g] = lo ? pack_bf16_lo(src[0], src[1]) : pack_bf16(src[0], src[1]);
        }
    } else if (blk < WH_BLOCKS + WL_BLOCKS + XH_BLOCKS + XL_BLOCKS) {
        const int xb = blk - WH_BLOCKS - WL_BLOCKS;
        const bool lo = xb >= XH_BLOCKS;
        const int base = (lo ? xb - XH_BLOCKS : xb) * 2048;
#pragma unroll
        for (int k = 0; k < 8; k++) {
            const int g = base + k * 256 + threadIdx.x;
            const int r = g & 1;
            const int lane = (g >> 1) & 31;
            const int rest = g >> 6;
            const int t = rest & 63;
            const int i = rest >> 6;
            const int gid = lane >> 2, tig = lane & 3;
            const int b = t * 16 + gid + r * 8;
            const float* src = x + (size_t)b * QTOT + i * 8 + tig * 2;
            (lo ? g_xl : g_xh)[g] = lo ? pack_bf16_lo(src[0], src[1]) : pack_bf16(src[0], src[1]);
        }
    } else if (blk < WH_BLOCKS + WL_BLOCKS + XH_BLOCKS + XL_BLOCKS + PX_BLOCKS) {
        const int pb = blk - WH_BLOCKS - WL_BLOCKS - XH_BLOCKS - XL_BLOCKS;
#pragma unroll
        for (int k = 0; k < 8; k++) {
            const int g = pb * 2048 + k * 256 + threadIdx.x;
            const int slab = g >> 13;
            const int r = g & 8191;
            const int b = r >> 3;
            const int q = r & 7;
            const int i = slab * 2 + (q & 1);
            const int e = (q >> 1) * 2;
            const float* src = x + (size_t)b * QTOT + i * 8 + e;
            g_xpair[g] = pack_bf16(src[0], src[1]);
        }
    } else {
        const int pb = blk - WH_BLOCKS - WL_BLOCKS - XH_BLOCKS - XL_BLOCKS - PX_BLOCKS;
#pragma unroll
        for (int k = 0; k < 8; k++) {
            const int g = pb * 2048 + k * 256 + threadIdx.x;
            const int slab = g / 1280;
            const int r = g % 1280;
            const int nd = r >> 3;
            const int q = r & 7;
            const int n = nd >> 4, d = nd & 15;
            const int i = slab * 2 + (q & 1);
            const int e = (q >> 1) * 2;
            const float* src = W + (((size_t)i * NOUT + n) * DOUT + d) * DIN + e;
            g_Wbf[g] = pack_bf16(src[0], src[1]);
        }
    }
}

// ---------------- pass 0 (uniform weights) — proven R9 GEMM ----------------
__global__ void __launch_bounds__(128) gemm_pass0()
{
    const int warp = threadIdx.x >> 5;
    const int lane = threadIdx.x & 31;
    const int gid = lane >> 2;
    const int tig = lane & 3;
    const int chunk = blockIdx.x;
    const int brow = blockIdx.y * 64 + warp * 16;
    const int slab0 = chunk * 16;

    float acc[20][4];
#pragma unroll
    for (int t = 0; t < 20; t++)
#pragma unroll
        for (int k = 0; k < 4; k++) acc[t][k] = 0.0f;

    for (int s = 0; s < 16; s++) {
        const uint32_t* __restrict__ xa =
            g_xpair + ((size_t)(slab0 + s) * BATCH + brow) * 8;
        const uint2 alo = *reinterpret_cast<const uint2*>(xa + gid * 8 + tig * 2);
        const uint2 ahi = *reinterpret_cast<const uint2*>(xa + (gid + 8) * 8 + tig * 2);
        const uint32_t a0 = alo.x, a2 = alo.y, a1 = ahi.x, a3 = ahi.y;

        const uint32_t* __restrict__ wb = g_Wbf + (size_t)(slab0 + s) * 160 * 8;
#pragma unroll
        for (int t = 0; t < 20; t++) {
            const uint2 bb = *reinterpret_cast<const uint2*>(wb + (t * 8 + gid) * 8 + tig * 2);
            hmma16816(acc[t], a0, a1, a2, a3, bb.x, bb.y);
        }
    }

    float* base0 = &g_partial[chunk][brow + gid][0][0];
    float* base1 = &g_partial[chunk][brow + gid + 8][0][0];
#pragma unroll
    for (int t = 0; t < 20; t++) {
        const int nd = t * 8 + tig * 2;
        *reinterpret_cast<float2*>(base0 + nd) = make_float2(acc[t][0], acc[t][1]);
        *reinterpret_cast<float2*>(base1 + nd) = make_float2(acc[t][2], acc[t][3]);
    }
}

// ---------------- passes 1-2: transposed-MMA fused routing pass ----------------
// A = x (M=16 batches), B = W (N=8 d, 2 tiles). Accumulator: (b=gid row, d cols
// in-thread) -> logit d-reduce is 4 in-thread FFMA + 2 shfl levels over tig.
#define RSI 2
#define RNSUB (CI / RSI)                 // 16

template <bool PRECISE>
__global__ void __launch_bounds__(320, 3) route_pass()
{
    constexpr int WSUB = 1280 * (PRECISE ? 2 : 1);   // u32 per W sub-buffer
    constexpr int XSZ  = 2048 * (PRECISE ? 2 : 1);   // u32 x tile
    extern __shared__ uint32_t smr[];
    uint32_t* ws  = smr;                  // [2][WSUB]
    uint32_t* xsm = smr + 2 * WSUB;       // [XSZ]

    const int tid  = threadIdx.x;
    const int n    = tid >> 5;
    const int lane = tid & 31;
    const int gid  = lane >> 2;
    const int tig  = lane & 3;
    const int chunk = blockIdx.x;
    const int i0    = chunk * CI;
    const int bt    = blockIdx.y;
    const int b0    = bt * 16;

    // stage x tile (hi, + lo if PRECISE)
#pragma unroll
    for (int k = 0; k < (PRECISE ? 4 : 2); k++) {
        const int idx = tid + k * 320;
        if (idx < XSZ / 4) {
            const int part = idx >> 9;               // 0 hi, 1 lo
            const int r = idx & 511;
            const int il = r >> 4, off = r & 15;
            const uint32_t* src = (part ? g_xl : g_xh) +
                ((size_t)(i0 + il) * 64 + bt) * 64 + off * 4;
            cpa16(xsm + part * 2048 + il * 64 + off * 4, src);
        }
    }
    // stage W sub 0 (320 uint4 hi; +320 lo)
    cpa16(ws + tid * 4, g_Wh + (size_t)i0 * 640 + tid * 4);
    if (PRECISE)
        cpa16(ws + 1280 + tid * 4, g_Wl + (size_t)i0 * 640 + tid * 4);
    cpa_commit();

    // V (pre-scaled by log2 e): V0 = b gid, V1 = b gid+8; d = {2tig,2tig+1,2tig+8,2tig+9}
    const float L2E = 1.4426950408889634f;
    float V0[4], V1[4];
    {
        float2 va = *reinterpret_cast<const float2*>(&g_vsum[b0 + gid][n][2 * tig]);
        float2 vb = *reinterpret_cast<const float2*>(&g_vsum[b0 + gid][n][2 * tig + 8]);
        float2 vc = *reinterpret_cast<const float2*>(&g_vsum[b0 + gid + 8][n][2 * tig]);
        float2 vd = *reinterpret_cast<const float2*>(&g_vsum[b0 + gid + 8][n][2 * tig + 8]);
        V0[0] = va.x * L2E; V0[1] = va.y * L2E; V0[2] = vb.x * L2E; V0[3] = vb.y * L2E;
        V1[0] = vc.x * L2E; V1[1] = vc.y * L2E; V1[2] = vd.x * L2E; V1[3] = vd.y * L2E;
    }

    float s0[4] = {0, 0, 0, 0}, s1[4] = {0, 0, 0, 0};
    float den0 = 0.0f, den1 = 0.0f;

    for (int s = 0; s < RNSUB; s++) {
        if (s + 1 < RNSUB) {
            uint32_t* dst = ws + ((s + 1) & 1) * WSUB;
            const size_t srcoff = (size_t)(i0 + (s + 1) * RSI) * 640;
            cpa16(dst + tid * 4, g_Wh + srcoff + tid * 4);
            if (PRECISE)
                cpa16(dst + 1280 + tid * 4, g_Wl + srcoff + tid * 4);
            cpa_commit();
            cpa_wait<1>();
        } else {
            cpa_wait<0>();
        }
        __syncthreads();

        const uint32_t* __restrict__ wsb = ws + (s & 1) * WSUB;
#pragma unroll
        for (int ii = 0; ii < RSI; ii++) {
            const uint2 Xh = *reinterpret_cast<const uint2*>(
                xsm + (s * RSI + ii) * 64 + lane * 2);
            const uint2 Wh = *reinterpret_cast<const uint2*>(
                wsb + (ii * NOUT + n) * 64 + lane * 2);

            float u0[4] = {0, 0, 0, 0}, u1[4] = {0, 0, 0, 0};
            hmma1688(u0, Xh.x, Xh.y, Wh.x);     // d tile 0 (0-7)
            hmma1688(u1, Xh.x, Xh.y, Wh.y);     // d tile 1 (8-15)
            if (PRECISE) {
                const uint2 Xl = *reinterpret_cast<const uint2*>(
                    xsm + 2048 + (s * RSI + ii) * 64 + lane * 2);
                const uint2 Wl = *reinterpret_cast<const uint2*>(
                    wsb + 1280 + (ii * NOUT + n) * 64 + lane * 2);
                hmma1688(u0, Xh.x, Xh.y, Wl.x);   // hi*lo
                hmma1688(u0, Xl.x, Xl.y, Wh.x);   // lo*hi
                hmma1688(u1, Xh.x, Xh.y, Wl.y);
                hmma1688(u1, Xl.x, Xl.y, Wh.y);
            }

            // logit partials: 4 d's in-thread per b-row
            float p0 = u0[0] * V0[0] + u0[1] * V0[1] + u1[0] * V0[2] + u1[1] * V0[3];
            float p1 = u0[2] * V1[0] + u0[3] * V1[1] + u1[2] * V1[2] + u1[3] * V1[3];
            p0 += __shfl_xor_sync(0xffffffffu, p0, 1);
            p0 += __shfl_xor_sync(0xffffffffu, p0, 2);
            p1 += __shfl_xor_sync(0xffffffffu, p1, 1);
            p1 += __shfl_xor_sync(0xffffffffu, p1, 2);
            const float w0 = ex2f(p0);   // logits O(10): no max-shift needed
            const float w1 = ex2f(p1);

            s0[0] += w0 * u0[0]; s0[1] += w0 * u0[1];
            s0[2] += w1 * u0[2]; s0[3] += w1 * u0[3];
            s1[0] += w0 * u1[0]; s1[1] += w0 * u1[1];
            s1[2] += w1 * u1[2]; s1[3] += w1 * u1[3];
            den0 += w0; den1 += w1;
        }
        __syncthreads();
    }

    *reinterpret_cast<float2*>(&g_partial[chunk][b0 + gid][n][2 * tig])         = make_float2(s0[0], s0[1]);
    *reinterpret_cast<float2*>(&g_partial[chunk][b0 + gid][n][2 * tig + 8])     = make_float2(s1[0], s1[1]);
    *reinterpret_cast<float2*>(&g_partial[chunk][b0 + gid + 8][n][2 * tig])     = make_float2(s0[2], s0[3]);
    *reinterpret_cast<float2*>(&g_partial[chunk][b0 + gid + 8][n][2 * tig + 8]) = make_float2(s1[2], s1[3]);
    if (tig == 0) {
        g_pden[chunk][b0 + gid][n]     = den0;
        g_pden[chunk][b0 + gid + 8][n] = den1;
    }
}

// ---------------- squash / vsum update ----------------
template <bool FIRST, bool LAST>
__global__ void __launch_bounds__(NOUT * DOUT)
squash_update(float* __restrict__ out)
{
    const int b = blockIdx.x;
    const int tid = threadIdx.x;
    const int n = tid >> 4;
    const int d = tid & 15;

    float num = 0.0f;
#pragma unroll
    for (int c = 0; c < NCHUNK; c++) num += g_partial[c][b][n][d];

    float den;
    if (FIRST) {
        den = (float)NIN;
    } else {
        den = 0.0f;
#pragma unroll
        for (int c = 0; c < NCHUNK; c++) den += g_pden[c][b][n];
    }

    const float s = num / den;

    float s2 = s * s;
#pragma unroll
    for (int off = 8; off; off >>= 1) s2 += __shfl_xor_sync(0xffffffffu, s2, off);

    const float scale = s2 / (1.0f + s2) * rsqrtf(s2 + 1e-7f);
    const float v = scale * s;

    if (LAST)       out[((size_t)b * NOUT + n) * DOUT + d] = v;
    else if (FIRST) g_vsum[b][n][d] = v;
    else            g_vsum[b][n][d] += v;
}

extern "C" void kernel_launch(void* const* d_in, const int* in_sizes, int n_in,
                              void* d_out, int out_size)
{
    const float* x;
    const float* W;
    if (in_sizes[0] == BATCH * NIN * DIN) { x = (const float*)d_in[0]; W = (const float*)d_in[1]; }
    else                                  { x = (const float*)d_in[1]; W = (const float*)d_in[0]; }
    float* out = (float*)d_out;

    prep<<<WH_BLOCKS + WL_BLOCKS + XH_BLOCKS + XL_BLOCKS + PX_BLOCKS + PW_BLOCKS, 256>>>(x, W);

    gemm_pass0<<<dim3(NCHUNK, BATCH / 64), 128>>>();
    squash_update<true , false><<<BATCH, NOUT * DOUT>>>(out);

    constexpr int SM1 = (2 * 1280 + 2048) * 4;   // 18.4KB (pass 1)
    constexpr int SM2 = (2 * 2560 + 4096) * 4;   // 36.9KB (pass 2)
    route_pass<false><<<dim3(NCHUNK, BATCH / 16), 320, SM1>>>();
    squash_update<false, false><<<BATCH, NOUT * DOUT>>>(out);

    route_pass<true ><<<dim3(NCHUNK, BATCH / 16), 320, SM2>>>();
    squash_update<false, true ><<<BATCH, NOUT * DOUT>>>(out);
}

// round 13
// speedup vs baseline: 1.8632x; 1.0216x over previous
#include <cuda_runtime.h>
#include <cuda_bf16.h>
#include <cstdint>

#define BATCH 1024
#define NIN   1152
#define DIN   8
#define NOUT  10
#define DOUT  16
#define QTOT  (NIN * DIN)        // 9216
#define NCHUNK 36
#define CI     (NIN / NCHUNK)    // 32 i per chunk

// ---------------- static device scratch ----------------
__device__ float g_partial[NCHUNK][BATCH][NOUT][DOUT];
__device__ float g_pden[NCHUNK][BATCH][NOUT];
__device__ float g_vsum[BATCH][NOUT][DOUT];
// pass-0 GEMM operands (k16, 2 i per slab) — proven R9
#define GSLABS_TOT (NIN / 2)
__device__ uint32_t g_xpair[GSLABS_TOT * BATCH * 8];
__device__ uint32_t g_Wbf[GSLABS_TOT * 160 * 8];
// passes 1-2: m16n8k8 fragments, hi/lo SPLIT arrays (layouts proven R12)
__device__ uint32_t g_Wh[NIN * NOUT * 64];
__device__ uint32_t g_Wl[NIN * NOUT * 64];
__device__ uint32_t g_xh[NIN * 64 * 64];
__device__ uint32_t g_xl[NIN * 64 * 64];

// ---------------- cp.async ----------------
__device__ __forceinline__ void cpa16(void* smem_dst, const void* gmem_src) {
    unsigned s = (unsigned)__cvta_generic_to_shared(smem_dst);
    asm volatile("cp.async.cg.shared.global [%0], [%1], 16;" :: "r"(s), "l"(gmem_src));
}
__device__ __forceinline__ void cpa_commit() { asm volatile("cp.async.commit_group;"); }
template <int N> __device__ __forceinline__ void cpa_wait() {
    asm volatile("cp.async.wait_group %0;" :: "n"(N));
}

// ---------------- mma helpers ----------------
__device__ __forceinline__ void hmma16816(float* c, uint32_t a0, uint32_t a1,
                                          uint32_t a2, uint32_t a3,
                                          uint32_t b0, uint32_t b1) {
    asm volatile(
        "mma.sync.aligned.m16n8k16.row.col.f32.bf16.bf16.f32 "
        "{%0,%1,%2,%3}, {%4,%5,%6,%7}, {%8,%9}, {%0,%1,%2,%3};"
        : "+f"(c[0]), "+f"(c[1]), "+f"(c[2]), "+f"(c[3])
        : "r"(a0), "r"(a1), "r"(a2), "r"(a3), "r"(b0), "r"(b1));
}
__device__ __forceinline__ void hmma1688(float* c, uint32_t a0, uint32_t a1, uint32_t b0) {
    asm volatile(
        "mma.sync.aligned.m16n8k8.row.col.f32.bf16.bf16.f32 "
        "{%0,%1,%2,%3}, {%4,%5}, {%6}, {%0,%1,%2,%3};"
        : "+f"(c[0]), "+f"(c[1]), "+f"(c[2]), "+f"(c[3])
        : "r"(a0), "r"(a1), "r"(b0));
}
__device__ __forceinline__ float ex2f(float x) {
    float r; asm("ex2.approx.f32 %0, %1;" : "=f"(r) : "f"(x)); return r;
}

__device__ __forceinline__ uint32_t pack_bf16(float f0, float f1) {
    __nv_bfloat162 h = __float22bfloat162_rn(make_float2(f0, f1));
    return *reinterpret_cast<uint32_t*>(&h);
}
__device__ __forceinline__ uint32_t pack_bf16_lo(float f0, float f1) {
    float h0 = __bfloat162float(__float2bfloat16_rn(f0));
    float h1 = __bfloat162float(__float2bfloat16_rn(f1));
    return pack_bf16(f0 - h0, f1 - h1);
}

// ---------------- prep (unchanged, layouts proven) ----------------
#define WH_BLOCKS 360
#define WL_BLOCKS 360
#define XH_BLOCKS 2304
#define XL_BLOCKS 2304
#define PX_BLOCKS 2304
#define PW_BLOCKS 360
__global__ void prep(const float* __restrict__ x, const float* __restrict__ W)
{
    const int blk = blockIdx.x;
    if (blk < WH_BLOCKS + WL_BLOCKS) {
        const bool lo = blk >= WH_BLOCKS;
        const int base = (lo ? blk - WH_BLOCKS : blk) * 2048;
#pragma unroll
        for (int k = 0; k < 8; k++) {
            const int g = base + k * 256 + threadIdx.x;
            const int r = g & 1;
            const int lane = (g >> 1) & 31;
            const int in = g >> 6;
            const int gid = lane >> 2, tig = lane & 3;
            const int d = gid + r * 8;
            const float* src = W + ((size_t)in * 16 + d) * 8 + tig * 2;
            (lo ? g_Wl : g_Wh)[g] = lo ? pack_bf16_lo(src[0], src[1]) : pack_bf16(src[0], src[1]);
        }
    } else if (blk < WH_BLOCKS + WL_BLOCKS + XH_BLOCKS + XL_BLOCKS) {
        const int xb = blk - WH_BLOCKS - WL_BLOCKS;
        const bool lo = xb >= XH_BLOCKS;
        const int base = (lo ? xb - XH_BLOCKS : xb) * 2048;
#pragma unroll
        for (int k = 0; k < 8; k++) {
            const int g = base + k * 256 + threadIdx.x;
            const int r = g & 1;
            const int lane = (g >> 1) & 31;
            const int rest = g >> 6;
            const int t = rest & 63;
            const int i = rest >> 6;
            const int gid = lane >> 2, tig = lane & 3;
            const int b = t * 16 + gid + r * 8;
            const float* src = x + (size_t)b * QTOT + i * 8 + tig * 2;
            (lo ? g_xl : g_xh)[g] = lo ? pack_bf16_lo(src[0], src[1]) : pack_bf16(src[0], src[1]);
        }
    } else if (blk < WH_BLOCKS + WL_BLOCKS + XH_BLOCKS + XL_BLOCKS + PX_BLOCKS) {
        const int pb = blk - WH_BLOCKS - WL_BLOCKS - XH_BLOCKS - XL_BLOCKS;
#pragma unroll
        for (int k = 0; k < 8; k++) {
            const int g = pb * 2048 + k * 256 + threadIdx.x;
            const int slab = g >> 13;
            const int r = g & 8191;
            const int b = r >> 3;
            const int q = r & 7;
            const int i = slab * 2 + (q & 1);
            const int e = (q >> 1) * 2;
            const float* src = x + (size_t)b * QTOT + i * 8 + e;
            g_xpair[g] = pack_bf16(src[0], src[1]);
        }
    } else {
        const int pb = blk - WH_BLOCKS - WL_BLOCKS - XH_BLOCKS - XL_BLOCKS - PX_BLOCKS;
#pragma unroll
        for (int k = 0; k < 8; k++) {
            const int g = pb * 2048 + k * 256 + threadIdx.x;
            const int slab = g / 1280;
            const int r = g % 1280;
            const int nd = r >> 3;
            const int q = r & 7;
            const int n = nd >> 4, d = nd & 15;
            const int i = slab * 2 + (q & 1);
            const int e = (q >> 1) * 2;
            const float* src = W + (((size_t)i * NOUT + n) * DOUT + d) * DIN + e;
            g_Wbf[g] = pack_bf16(src[0], src[1]);
        }
    }
}

// ---------------- pass 0 (uniform weights) — proven R9 GEMM ----------------
__global__ void __launch_bounds__(128) gemm_pass0()
{
    const int warp = threadIdx.x >> 5;
    const int lane = threadIdx.x & 31;
    const int gid = lane >> 2;
    const int tig = lane & 3;
    const int chunk = blockIdx.x;
    const int brow = blockIdx.y * 64 + warp * 16;
    const int slab0 = chunk * 16;

    float acc[20][4];
#pragma unroll
    for (int t = 0; t < 20; t++)
#pragma unroll
        for (int k = 0; k < 4; k++) acc[t][k] = 0.0f;

    for (int s = 0; s < 16; s++) {
        const uint32_t* __restrict__ xa =
            g_xpair + ((size_t)(slab0 + s) * BATCH + brow) * 8;
        const uint2 alo = *reinterpret_cast<const uint2*>(xa + gid * 8 + tig * 2);
        const uint2 ahi = *reinterpret_cast<const uint2*>(xa + (gid + 8) * 8 + tig * 2);
        const uint32_t a0 = alo.x, a2 = alo.y, a1 = ahi.x, a3 = ahi.y;

        const uint32_t* __restrict__ wb = g_Wbf + (size_t)(slab0 + s) * 160 * 8;
#pragma unroll
        for (int t = 0; t < 20; t++) {
            const uint2 bb = *reinterpret_cast<const uint2*>(wb + (t * 8 + gid) * 8 + tig * 2);
            hmma16816(acc[t], a0, a1, a2, a3, bb.x, bb.y);
        }
    }

    float* base0 = &g_partial[chunk][brow + gid][0][0];
    float* base1 = &g_partial[chunk][brow + gid + 8][0][0];
#pragma unroll
    for (int t = 0; t < 20; t++) {
        const int nd = t * 8 + tig * 2;
        *reinterpret_cast<float2*>(base0 + nd) = make_float2(acc[t][0], acc[t][1]);
        *reinterpret_cast<float2*>(base1 + nd) = make_float2(acc[t][2], acc[t][3]);
    }
}

// ---------------- passes 1-2: transposed-MMA fused routing pass ----------------
#define RSI 2
#define RNSUB (CI / RSI)                 // 16

template <bool PRECISE>
__device__ __forceinline__ void route_impl()
{
    constexpr int WSUB = 1280 * (PRECISE ? 2 : 1);
    constexpr int XSZ  = 2048 * (PRECISE ? 2 : 1);
    extern __shared__ uint32_t smr[];
    uint32_t* ws  = smr;
    uint32_t* xsm = smr + 2 * WSUB;

    const int tid  = threadIdx.x;
    const int n    = tid >> 5;
    const int lane = tid & 31;
    const int gid  = lane >> 2;
    const int tig  = lane & 3;
    const int chunk = blockIdx.x;
    const int i0    = chunk * CI;
    const int bt    = blockIdx.y;
    const int b0    = bt * 16;

    // stage x tile (hi, + lo if PRECISE)
#pragma unroll
    for (int k = 0; k < (PRECISE ? 4 : 2); k++) {
        const int idx = tid + k * 320;
        if (idx < XSZ / 4) {
            const int part = idx >> 9;
            const int r = idx & 511;
            const int il = r >> 4, off = r & 15;
            const uint32_t* src = (part ? g_xl : g_xh) +
                ((size_t)(i0 + il) * 64 + bt) * 64 + off * 4;
            cpa16(xsm + part * 2048 + il * 64 + off * 4, src);
        }
    }
    // stage W sub 0
    cpa16(ws + tid * 4, g_Wh + (size_t)i0 * 640 + tid * 4);
    if (PRECISE)
        cpa16(ws + 1280 + tid * 4, g_Wl + (size_t)i0 * 640 + tid * 4);
    cpa_commit();

    const float L2E = 1.4426950408889634f;
    float V0[4], V1[4];
    {
        float2 va = *reinterpret_cast<const float2*>(&g_vsum[b0 + gid][n][2 * tig]);
        float2 vb = *reinterpret_cast<const float2*>(&g_vsum[b0 + gid][n][2 * tig + 8]);
        float2 vc = *reinterpret_cast<const float2*>(&g_vsum[b0 + gid + 8][n][2 * tig]);
        float2 vd = *reinterpret_cast<const float2*>(&g_vsum[b0 + gid + 8][n][2 * tig + 8]);
        V0[0] = va.x * L2E; V0[1] = va.y * L2E; V0[2] = vb.x * L2E; V0[3] = vb.y * L2E;
        V1[0] = vc.x * L2E; V1[1] = vc.y * L2E; V1[2] = vd.x * L2E; V1[3] = vd.y * L2E;
    }

    float s0[4] = {0, 0, 0, 0}, s1[4] = {0, 0, 0, 0};
    float den0 = 0.0f, den1 = 0.0f;

    for (int s = 0; s < RNSUB; s++) {
        if (s + 1 < RNSUB) {
            uint32_t* dst = ws + ((s + 1) & 1) * WSUB;
            const size_t srcoff = (size_t)(i0 + (s + 1) * RSI) * 640;
            cpa16(dst + tid * 4, g_Wh + srcoff + tid * 4);
            if (PRECISE)
                cpa16(dst + 1280 + tid * 4, g_Wl + srcoff + tid * 4);
            cpa_commit();
            cpa_wait<1>();
        } else {
            cpa_wait<0>();
        }
        __syncthreads();

        const uint32_t* __restrict__ wsb = ws + (s & 1) * WSUB;
#pragma unroll
        for (int ii = 0; ii < RSI; ii++) {
            const uint2 Xh = *reinterpret_cast<const uint2*>(
                xsm + (s * RSI + ii) * 64 + lane * 2);
            const uint2 Wh = *reinterpret_cast<const uint2*>(
                wsb + (ii * NOUT + n) * 64 + lane * 2);

            float u0[4] = {0, 0, 0, 0}, u1[4] = {0, 0, 0, 0};
            hmma1688(u0, Xh.x, Xh.y, Wh.x);     // hi*hi, d tile 0
            hmma1688(u1, Xh.x, Xh.y, Wh.y);     // hi*hi, d tile 1
            if (PRECISE) {
                const uint2 Xl = *reinterpret_cast<const uint2*>(
                    xsm + 2048 + (s * RSI + ii) * 64 + lane * 2);
                const uint2 Wl = *reinterpret_cast<const uint2*>(
                    wsb + 1280 + (ii * NOUT + n) * 64 + lane * 2);
                // mixed term xh*wl + xl*wh in ONE k16 MMA per d-tile:
                // A = [Xh | Xl] (k-low | k-high), B = [Wl | Wh]
                hmma16816(u0, Xh.x, Xh.y, Xl.x, Xl.y, Wl.x, Wh.x);
                hmma16816(u1, Xh.x, Xh.y, Xl.x, Xl.y, Wl.y, Wh.y);
            }

            float p0 = u0[0] * V0[0] + u0[1] * V0[1] + u1[0] * V0[2] + u1[1] * V0[3];
            float p1 = u0[2] * V1[0] + u0[3] * V1[1] + u1[2] * V1[2] + u1[3] * V1[3];
            p0 += __shfl_xor_sync(0xffffffffu, p0, 1);
            p0 += __shfl_xor_sync(0xffffffffu, p0, 2);
            p1 += __shfl_xor_sync(0xffffffffu, p1, 1);
            p1 += __shfl_xor_sync(0xffffffffu, p1, 2);
            const float w0 = ex2f(p0);   // logits O(10): no max-shift needed
            const float w1 = ex2f(p1);

            s0[0] += w0 * u0[0]; s0[1] += w0 * u0[1];
            s0[2] += w1 * u0[2]; s0[3] += w1 * u0[3];
            s1[0] += w0 * u1[0]; s1[1] += w0 * u1[1];
            s1[2] += w1 * u1[2]; s1[3] += w1 * u1[3];
            den0 += w0; den1 += w1;
        }
        __syncthreads();
    }

    *reinterpret_cast<float2*>(&g_partial[chunk][b0 + gid][n][2 * tig])         = make_float2(s0[0], s0[1]);
    *reinterpret_cast<float2*>(&g_partial[chunk][b0 + gid][n][2 * tig + 8])     = make_float2(s1[0], s1[1]);
    *reinterpret_cast<float2*>(&g_partial[chunk][b0 + gid + 8][n][2 * tig])     = make_float2(s0[2], s0[3]);
    *reinterpret_cast<float2*>(&g_partial[chunk][b0 + gid + 8][n][2 * tig + 8]) = make_float2(s1[2], s1[3]);
    if (tig == 0) {
        g_pden[chunk][b0 + gid][n]     = den0;
        g_pden[chunk][b0 + gid + 8][n] = den1;
    }
}

// pass 1 (bf16 steering): force 4 CTAs/SM; pass 2 (bf16x3): 3 CTAs/SM
__global__ void __launch_bounds__(320, 4) route_pass1() { route_impl<false>(); }
__global__ void __launch_bounds__(320, 3) route_pass2() { route_impl<true>(); }

// ---------------- squash / vsum update ----------------
template <bool FIRST, bool LAST>
__global__ void __launch_bounds__(NOUT * DOUT)
squash_update(float* __restrict__ out)
{
    const int b = blockIdx.x;
    const int tid = threadIdx.x;
    const int n = tid >> 4;
    const int d = tid & 15;

    float num = 0.0f;
#pragma unroll
    for (int c = 0; c < NCHUNK; c++) num += g_partial[c][b][n][d];

    float den;
    if (FIRST) {
        den = (float)NIN;
    } else {
        den = 0.0f;
#pragma unroll
        for (int c = 0; c < NCHUNK; c++) den += g_pden[c][b][n];
    }

    const float s = num / den;

    float s2 = s * s;
#pragma unroll
    for (int off = 8; off; off >>= 1) s2 += __shfl_xor_sync(0xffffffffu, s2, off);

    const float scale = s2 / (1.0f + s2) * rsqrtf(s2 + 1e-7f);
    const float v = scale * s;

    if (LAST)       out[((size_t)b * NOUT + n) * DOUT + d] = v;
    else if (FIRST) g_vsum[b][n][d] = v;
    else            g_vsum[b][n][d] += v;
}

extern "C" void kernel_launch(void* const* d_in, const int* in_sizes, int n_in,
                              void* d_out, int out_size)
{
    const float* x;
    const float* W;
    if (in_sizes[0] == BATCH * NIN * DIN) { x = (const float*)d_in[0]; W = (const float*)d_in[1]; }
    else                                  { x = (const float*)d_in[1]; W = (const float*)d_in[0]; }
    float* out = (float*)d_out;

    prep<<<WH_BLOCKS + WL_BLOCKS + XH_BLOCKS + XL_BLOCKS + PX_BLOCKS + PW_BLOCKS, 256>>>(x, W);

    gemm_pass0<<<dim3(NCHUNK, BATCH / 64), 128>>>();
    squash_update<true , false><<<BATCH, NOUT * DOUT>>>(out);

    constexpr int SM1 = (2 * 1280 + 2048) * 4;   // 18.4KB
    constexpr int SM2 = (2 * 2560 + 4096) * 4;   // 36.9KB
    route_pass1<<<dim3(NCHUNK, BATCH / 16), 320, SM1>>>();
    squash_update<false, false><<<BATCH, NOUT * DOUT>>>(out);

    route_pass2<<<dim3(NCHUNK, BATCH / 16), 320, SM2>>>();
    squash_update<false, true ><<<BATCH, NOUT * DOUT>>>(out);
}

// round 15
// speedup vs baseline: 2.0035x; 1.0753x over previous
#include <cuda_runtime.h>
#include <cuda_bf16.h>
#include <cstdint>

#define BATCH 1024
#define NIN   1152
#define DIN   8
#define NOUT  10
#define DOUT  16
#define QTOT  (NIN * DIN)        // 9216
#define NCHUNK 36
#define CI     (NIN / NCHUNK)    // 32 i per chunk

// ---------------- static device scratch ----------------
__device__ float g_partial[NCHUNK][BATCH][NOUT][DOUT];
__device__ float g_pden[NCHUNK][BATCH][NOUT];
__device__ float g_vsum[BATCH][NOUT][DOUT];
// pass-0 GEMM operands (k16, 2 i per slab) — proven R9
#define GSLABS_TOT (NIN / 2)
__device__ uint32_t g_xpair[GSLABS_TOT * BATCH * 8];
__device__ uint32_t g_Wbf[GSLABS_TOT * 160 * 8];
// passes 1-2: m16n8k8 fragments, hi/lo SPLIT arrays (layouts proven R12)
__device__ uint32_t g_Wh[NIN * NOUT * 64];
__device__ uint32_t g_Wl[NIN * NOUT * 64];
__device__ uint32_t g_xh[NIN * 64 * 64];
__device__ uint32_t g_xl[NIN * 64 * 64];

// ---------------- cp.async ----------------
__device__ __forceinline__ void cpa16(void* smem_dst, const void* gmem_src) {
    unsigned s = (unsigned)__cvta_generic_to_shared(smem_dst);
    asm volatile("cp.async.cg.shared.global [%0], [%1], 16;" :: "r"(s), "l"(gmem_src));
}
__device__ __forceinline__ void cpa_commit() { asm volatile("cp.async.commit_group;"); }
template <int N> __device__ __forceinline__ void cpa_wait() {
    asm volatile("cp.async.wait_group %0;" :: "n"(N));
}

// ---------------- mma helpers ----------------
__device__ __forceinline__ void hmma16816(float* c, uint32_t a0, uint32_t a1,
                                          uint32_t a2, uint32_t a3,
                                          uint32_t b0, uint32_t b1) {
    asm volatile(
        "mma.sync.aligned.m16n8k16.row.col.f32.bf16.bf16.f32 "
        "{%0,%1,%2,%3}, {%4,%5,%6,%7}, {%8,%9}, {%0,%1,%2,%3};"
        : "+f"(c[0]), "+f"(c[1]), "+f"(c[2]), "+f"(c[3])
        : "r"(a0), "r"(a1), "r"(a2), "r"(a3), "r"(b0), "r"(b1));
}
__device__ __forceinline__ void hmma1688(float* c, uint32_t a0, uint32_t a1, uint32_t b0) {
    asm volatile(
        "mma.sync.aligned.m16n8k8.row.col.f32.bf16.bf16.f32 "
        "{%0,%1,%2,%3}, {%4,%5}, {%6}, {%0,%1,%2,%3};"
        : "+f"(c[0]), "+f"(c[1]), "+f"(c[2]), "+f"(c[3])
        : "r"(a0), "r"(a1), "r"(b0));
}
__device__ __forceinline__ float ex2f(float x) {
    float r; asm("ex2.approx.f32 %0, %1;" : "=f"(r) : "f"(x)); return r;
}

__device__ __forceinline__ uint32_t pack_bf16(float f0, float f1) {
    __nv_bfloat162 h = __float22bfloat162_rn(make_float2(f0, f1));
    return *reinterpret_cast<uint32_t*>(&h);
}
__device__ __forceinline__ uint32_t pack_bf16_lo(float f0, float f1) {
    float h0 = __bfloat162float(__float2bfloat16_rn(f0));
    float h1 = __bfloat162float(__float2bfloat16_rn(f1));
    return pack_bf16(f0 - h0, f1 - h1);
}

// ---------------- prep (unchanged, layouts proven) ----------------
#define WH_BLOCKS 360
#define WL_BLOCKS 360
#define XH_BLOCKS 2304
#define XL_BLOCKS 2304
#define PX_BLOCKS 2304
#define PW_BLOCKS 360
__global__ void prep(const float* __restrict__ x, const float* __restrict__ W)
{
    const int blk = blockIdx.x;
    if (blk < WH_BLOCKS + WL_BLOCKS) {
        const bool lo = blk >= WH_BLOCKS;
        const int base = (lo ? blk - WH_BLOCKS : blk) * 2048;
#pragma unroll
        for (int k = 0; k < 8; k++) {
            const int g = base + k * 256 + threadIdx.x;
            const int r = g & 1;
            const int lane = (g >> 1) & 31;
            const int in = g >> 6;
            const int gid = lane >> 2, tig = lane & 3;
            const int d = gid + r * 8;
            const float* src = W + ((size_t)in * 16 + d) * 8 + tig * 2;
            (lo ? g_Wl : g_Wh)[g] = lo ? pack_bf16_lo(src[0], src[1]) : pack_bf16(src[0], src[1]);
        }
    } else if (blk < WH_BLOCKS + WL_BLOCKS + XH_BLOCKS + XL_BLOCKS) {
        const int xb = blk - WH_BLOCKS - WL_BLOCKS;
        const bool lo = xb >= XH_BLOCKS;
        const int base = (lo ? xb - XH_BLOCKS : xb) * 2048;
#pragma unroll
        for (int k = 0; k < 8; k++) {
            const int g = base + k * 256 + threadIdx.x;
            const int r = g & 1;
            const int lane = (g >> 1) & 31;
            const int rest = g >> 6;
            const int t = rest & 63;
            const int i = rest >> 6;
            const int gid = lane >> 2, tig = lane & 3;
            const int b = t * 16 + gid + r * 8;
            const float* src = x + (size_t)b * QTOT + i * 8 + tig * 2;
            (lo ? g_xl : g_xh)[g] = lo ? pack_bf16_lo(src[0], src[1]) : pack_bf16(src[0], src[1]);
        }
    } else if (blk < WH_BLOCKS + WL_BLOCKS + XH_BLOCKS + XL_BLOCKS + PX_BLOCKS) {
        const int pb = blk - WH_BLOCKS - WL_BLOCKS - XH_BLOCKS - XL_BLOCKS;
#pragma unroll
        for (int k = 0; k < 8; k++) {
            const int g = pb * 2048 + k * 256 + threadIdx.x;
            const int slab = g >> 13;
            const int r = g & 8191;
            const int b = r >> 3;
            const int q = r & 7;
            const int i = slab * 2 + (q & 1);
            const int e = (q >> 1) * 2;
            const float* src = x + (size_t)b * QTOT + i * 8 + e;
            g_xpair[g] = pack_bf16(src[0], src[1]);
        }
    } else {
        const int pb = blk - WH_BLOCKS - WL_BLOCKS - XH_BLOCKS - XL_BLOCKS - PX_BLOCKS;
#pragma unroll
        for (int k = 0; k < 8; k++) {
            const int g = pb * 2048 + k * 256 + threadIdx.x;
            const int slab = g / 1280;
            const int r = g % 1280;
            const int nd = r >> 3;
            const int q = r & 7;
            const int n = nd >> 4, d = nd & 15;
            const int i = slab * 2 + (q & 1);
            const int e = (q >> 1) * 2;
            const float* src = W + (((size_t)i * NOUT + n) * DOUT + d) * DIN + e;
            g_Wbf[g] = pack_bf16(src[0], src[1]);
        }
    }
}

// ---------------- pass 0 (uniform weights) — proven R9 GEMM ----------------
__global__ void __launch_bounds__(128) gemm_pass0()
{
    const int warp = threadIdx.x >> 5;
    const int lane = threadIdx.x & 31;
    const int gid = lane >> 2;
    const int tig = lane & 3;
    const int chunk = blockIdx.x;
    const int brow = blockIdx.y * 64 + warp * 16;
    const int slab0 = chunk * 16;

    float acc[20][4];
#pragma unroll
    for (int t = 0; t < 20; t++)
#pragma unroll
        for (int k = 0; k < 4; k++) acc[t][k] = 0.0f;

    for (int s = 0; s < 16; s++) {
        const uint32_t* __restrict__ xa =
            g_xpair + ((size_t)(slab0 + s) * BATCH + brow) * 8;
        const uint2 alo = *reinterpret_cast<const uint2*>(xa + gid * 8 + tig * 2);
        const uint2 ahi = *reinterpret_cast<const uint2*>(xa + (gid + 8) * 8 + tig * 2);
        const uint32_t a0 = alo.x, a2 = alo.y, a1 = ahi.x, a3 = ahi.y;

        const uint32_t* __restrict__ wb = g_Wbf + (size_t)(slab0 + s) * 160 * 8;
#pragma unroll
        for (int t = 0; t < 20; t++) {
            const uint2 bb = *reinterpret_cast<const uint2*>(wb + (t * 8 + gid) * 8 + tig * 2);
            hmma16816(acc[t], a0, a1, a2, a3, bb.x, bb.y);
        }
    }

    float* base0 = &g_partial[chunk][brow + gid][0][0];
    float* base1 = &g_partial[chunk][brow + gid + 8][0][0];
#pragma unroll
    for (int t = 0; t < 20; t++) {
        const int nd = t * 8 + tig * 2;
        *reinterpret_cast<float2*>(base0 + nd) = make_float2(acc[t][0], acc[t][1]);
        *reinterpret_cast<float2*>(base1 + nd) = make_float2(acc[t][2], acc[t][3]);
    }
}

// ---------------- passes 1-2: transposed-MMA fused routing pass ----------------
// RSI=4: four independent per-i chains in flight per stage (ILP over shfl/ex2),
// row pointers hoisted so inner offsets are compile-time immediates.
#define RSI 4
#define RNSUB (CI / RSI)                 // 8

template <bool PRECISE>
__device__ __forceinline__ void route_impl()
{
    constexpr int WHALF = RSI * NOUT * 64;              // 2560 u32 (hi part)
    constexpr int WSUB  = WHALF * (PRECISE ? 2 : 1);    // per-buffer u32
    constexpr int XSZ   = 2048 * (PRECISE ? 2 : 1);
    extern __shared__ uint32_t smr[];
    uint32_t* ws  = smr;
    uint32_t* xsm = smr + 2 * WSUB;

    const int tid  = threadIdx.x;
    const int n    = tid >> 5;
    const int lane = tid & 31;
    const int gid  = lane >> 2;
    const int tig  = lane & 3;
    const int chunk = blockIdx.x;
    const int i0    = chunk * CI;
    const int bt    = blockIdx.y;
    const int b0    = bt * 16;

    // stage x tile (hi, + lo if PRECISE)
#pragma unroll
    for (int k = 0; k < (PRECISE ? 4 : 2); k++) {
        const int idx = tid + k * 320;
        if (idx < XSZ / 4) {
            const int part = idx >> 9;
            const int r = idx & 511;
            const int il = r >> 4, off = r & 15;
            const uint32_t* src = (part ? g_xl : g_xh) +
                ((size_t)(i0 + il) * 64 + bt) * 64 + off * 4;
            cpa16(xsm + part * 2048 + il * 64 + off * 4, src);
        }
    }
    // stage W sub 0
#pragma unroll
    for (int k = 0; k < 2; k++) {
        const int idx = tid + k * 320;
        cpa16(ws + idx * 4, g_Wh + (size_t)i0 * 640 + idx * 4);
        if (PRECISE)
            cpa16(ws + WHALF + idx * 4, g_Wl + (size_t)i0 * 640 + idx * 4);
    }
    cpa_commit();

    const float L2E = 1.4426950408889634f;
    float V0[4], V1[4];
    {
        float2 va = *reinterpret_cast<const float2*>(&g_vsum[b0 + gid][n][2 * tig]);
        float2 vb = *reinterpret_cast<const float2*>(&g_vsum[b0 + gid][n][2 * tig + 8]);
        float2 vc = *reinterpret_cast<const float2*>(&g_vsum[b0 + gid + 8][n][2 * tig]);
        float2 vd = *reinterpret_cast<const float2*>(&g_vsum[b0 + gid + 8][n][2 * tig + 8]);
        V0[0] = va.x * L2E; V0[1] = va.y * L2E; V0[2] = vb.x * L2E; V0[3] = vb.y * L2E;
        V1[0] = vc.x * L2E; V1[1] = vc.y * L2E; V1[2] = vd.x * L2E; V1[3] = vd.y * L2E;
    }

    float s0[4] = {0, 0, 0, 0}, s1[4] = {0, 0, 0, 0};
    float den0 = 0.0f, den1 = 0.0f;

    for (int s = 0; s < RNSUB; s++) {
        if (s + 1 < RNSUB) {
            uint32_t* dst = ws + ((s + 1) & 1) * WSUB;
            const size_t srcoff = (size_t)(i0 + (s + 1) * RSI) * 640;
#pragma unroll
            for (int k = 0; k < 2; k++) {
                const int idx = tid + k * 320;
                cpa16(dst + idx * 4, g_Wh + srcoff + idx * 4);
                if (PRECISE)
                    cpa16(dst + WHALF + idx * 4, g_Wl + srcoff + idx * 4);
            }
            cpa_commit();
            cpa_wait<1>();
        } else {
            cpa_wait<0>();
        }
        __syncthreads();

        // hoisted row pointers: inner offsets are compile-time immediates
        const uint32_t* __restrict__ wrow = ws + (s & 1) * WSUB + n * 64 + lane * 2;
        const uint32_t* __restrict__ xrow = xsm + s * (RSI * 64) + lane * 2;

#pragma unroll
        for (int ii = 0; ii < RSI; ii++) {
            const uint2 Xh = *reinterpret_cast<const uint2*>(xrow + ii * 64);
            const uint2 Wh = *reinterpret_cast<const uint2*>(wrow + ii * (NOUT * 64));

            float u0[4] = {0, 0, 0, 0}, u1[4] = {0, 0, 0, 0};
            hmma1688(u0, Xh.x, Xh.y, Wh.x);     // hi*hi, d tile 0
            hmma1688(u1, Xh.x, Xh.y, Wh.y);     // hi*hi, d tile 1
            if (PRECISE) {
                const uint2 Xl = *reinterpret_cast<const uint2*>(xrow + 2048 + ii * 64);
                const uint2 Wl = *reinterpret_cast<const uint2*>(wrow + WHALF + ii * (NOUT * 64));
                // mixed term xh*wl + xl*wh in ONE k16 MMA per d-tile
                hmma16816(u0, Xh.x, Xh.y, Xl.x, Xl.y, Wl.x, Wh.x);
                hmma16816(u1, Xh.x, Xh.y, Xl.x, Xl.y, Wl.y, Wh.y);
            }

            float p0 = u0[0] * V0[0] + u0[1] * V0[1] + u1[0] * V0[2] + u1[1] * V0[3];
            float p1 = u0[2] * V1[0] + u0[3] * V1[1] + u1[2] * V1[2] + u1[3] * V1[3];
            p0 += __shfl_xor_sync(0xffffffffu, p0, 1);
            p0 += __shfl_xor_sync(0xffffffffu, p0, 2);
            p1 += __shfl_xor_sync(0xffffffffu, p1, 1);
            p1 += __shfl_xor_sync(0xffffffffu, p1, 2);
            const float w0 = ex2f(p0);   // logits O(10): no max-shift needed
            const float w1 = ex2f(p1);

            s0[0] += w0 * u0[0]; s0[1] += w0 * u0[1];
            s0[2] += w1 * u0[2]; s0[3] += w1 * u0[3];
            s1[0] += w0 * u1[0]; s1[1] += w0 * u1[1];
            s1[2] += w1 * u1[2]; s1[3] += w1 * u1[3];
            den0 += w0; den1 += w1;
        }
        __syncthreads();
    }

    *reinterpret_cast<float2*>(&g_partial[chunk][b0 + gid][n][2 * tig])         = make_float2(s0[0], s0[1]);
    *reinterpret_cast<float2*>(&g_partial[chunk][b0 + gid][n][2 * tig + 8])     = make_float2(s1[0], s1[1]);
    *reinterpret_cast<float2*>(&g_partial[chunk][b0 + gid + 8][n][2 * tig])     = make_float2(s0[2], s0[3]);
    *reinterpret_cast<float2*>(&g_partial[chunk][b0 + gid + 8][n][2 * tig + 8]) = make_float2(s1[2], s1[3]);
    if (tig == 0) {
        g_pden[chunk][b0 + gid][n]     = den0;
        g_pden[chunk][b0 + gid + 8][n] = den1;
    }
}

// pass 1 (bf16 steering): 4 CTAs/SM; pass 2 (bf16x3): 3 CTAs/SM
__global__ void __launch_bounds__(320, 4) route_pass1() { route_impl<false>(); }
__global__ void __launch_bounds__(320, 3) route_pass2() { route_impl<true>(); }

// ---------------- squash / vsum update ----------------
template <bool FIRST, bool LAST>
__global__ void __launch_bounds__(NOUT * DOUT)
squash_update(float* __restrict__ out)
{
    const int b = blockIdx.x;
    const int tid = threadIdx.x;
    const int n = tid >> 4;
    const int d = tid & 15;

    float num = 0.0f;
#pragma unroll
    for (int c = 0; c < NCHUNK; c++) num += g_partial[c][b][n][d];

    float den;
    if (FIRST) {
        den = (float)NIN;
    } else {
        den = 0.0f;
#pragma unroll
        for (int c = 0; c < NCHUNK; c++) den += g_pden[c][b][n];
    }

    const float s = num / den;

    float s2 = s * s;
#pragma unroll
    for (int off = 8; off; off >>= 1) s2 += __shfl_xor_sync(0xffffffffu, s2, off);

    const float scale = s2 / (1.0f + s2) * rsqrtf(s2 + 1e-7f);
    const float v = scale * s;

    if (LAST)       out[((size_t)b * NOUT + n) * DOUT + d] = v;
    else if (FIRST) g_vsum[b][n][d] = v;
    else            g_vsum[b][n][d] += v;
}

extern "C" void kernel_launch(void* const* d_in, const int* in_sizes, int n_in,
                              void* d_out, int out_size)
{
    const float* x;
    const float* W;
    if (in_sizes[0] == BATCH * NIN * DIN) { x = (const float*)d_in[0]; W = (const float*)d_in[1]; }
    else                                  { x = (const float*)d_in[1]; W = (const float*)d_in[0]; }
    float* out = (float*)d_out;

    constexpr int SM1 = (2 * 2560 + 2048) * 4;   // 28.7KB (pass 1, < 48KB default)
    constexpr int SM2 = (2 * 5120 + 4096) * 4;   // 57.3KB (pass 2, NEEDS opt-in)

    // >48KB dynamic smem opt-in (host-side, idempotent, graph-safe; proven R3-R7)
    static bool attr_done = false;
    if (!attr_done) {
        cudaFuncSetAttribute(route_pass2, cudaFuncAttributeMaxDynamicSharedMemorySize, SM2);
        cudaFuncSetAttribute(route_pass1, cudaFuncAttributeMaxDynamicSharedMemorySize, SM1);
        attr_done = true;
    }

    prep<<<WH_BLOCKS + WL_BLOCKS + XH_BLOCKS + XL_BLOCKS + PX_BLOCKS + PW_BLOCKS, 256>>>(x, W);

    gemm_pass0<<<dim3(NCHUNK, BATCH / 64), 128>>>();
    squash_update<true , false><<<BATCH, NOUT * DOUT>>>(out);

    route_pass1<<<dim3(NCHUNK, BATCH / 16), 320, SM1>>>();
    squash_update<false, false><<<BATCH, NOUT * DOUT>>>(out);

    route_pass2<<<dim3(NCHUNK, BATCH / 16), 320, SM2>>>();
    squash_update<false, true ><<<BATCH, NOUT * DOUT>>>(out);
}